// round 11
// baseline (speedup 1.0000x reference)
#include <cuda_runtime.h>
#include <cuda_bf16.h>
#include <cstdint>

// Problem constants
#define Bq   4
#define Nq   2048
#define FIN  128
#define Hq   4
#define Dq   64
#define ALPHA 0.2f

// Scratch
__device__ float g_h[Bq * Hq * Nq * Dq];    // [bh][n][d] (8 MB)
__device__ float g_o[Bq * Hq * Nq * Dq];
__device__ float g_ei[Bq * Hq * Nq];
__device__ float g_ej[Bq * Hq * Nq];
__device__ int   g_sink;

// ---- packed f32x2 helpers (k_gemm) ----------------------------------------
__device__ __forceinline__ unsigned long long pk2(float lo, float hi) {
    unsigned long long r;
    asm("mov.b64 %0, {%1,%2};" : "=l"(r) : "f"(lo), "f"(hi));
    return r;
}
__device__ __forceinline__ void fma2(unsigned long long& d,
                                     unsigned long long a,
                                     unsigned long long b) {
    asm("fma.rn.f32x2 %0, %1, %2, %0;" : "+l"(d) : "l"(a), "l"(b));
}
__device__ __forceinline__ float2 upk(unsigned long long v) {
    float2 f;
    asm("mov.b64 {%0,%1}, %2;" : "=f"(f.x), "=f"(f.y) : "l"(v));
    return f;
}

// ---- mma.sync helpers -----------------------------------------------------
__device__ __forceinline__ uint32_t s2u(const void* p) {
    uint32_t a;
    asm("{ .reg .u64 t; cvta.to.shared.u64 t, %1; cvt.u32.u64 %0, t; }"
        : "=r"(a) : "l"(p));
    return a;
}
__device__ __forceinline__ void ldsm4(uint32_t* r, uint32_t a) {
    asm volatile("ldmatrix.sync.aligned.m8n8.x4.shared.b16 {%0,%1,%2,%3},[%4];"
                 : "=r"(r[0]), "=r"(r[1]), "=r"(r[2]), "=r"(r[3]) : "r"(a));
}
__device__ __forceinline__ void ldsm4t(uint32_t* r, uint32_t a) {
    asm volatile(
        "ldmatrix.sync.aligned.m8n8.x4.trans.shared.b16 {%0,%1,%2,%3},[%4];"
        : "=r"(r[0]), "=r"(r[1]), "=r"(r[2]), "=r"(r[3]) : "r"(a));
}
__device__ __forceinline__ void mmab(float* c, const uint32_t* a,
                                     const uint32_t* b) {
    asm volatile(
        "mma.sync.aligned.m16n8k16.row.col.f32.bf16.bf16.f32 "
        "{%0,%1,%2,%3},{%4,%5,%6,%7},{%8,%9},{%0,%1,%2,%3};"
        : "+f"(c[0]), "+f"(c[1]), "+f"(c[2]), "+f"(c[3])
        : "r"(a[0]), "r"(a[1]), "r"(a[2]), "r"(a[3]), "r"(b[0]), "r"(b[1]));
}
__device__ __forceinline__ uint32_t pbf(float x, float y) {
    __nv_bfloat162 t = __floats2bfloat162_rn(x, y);
    return *(uint32_t*)&t;
}

// ---------------------------------------------------------------------------
// Kernel 1: h = x @ W -> g_h[b][head][n][d]
// ---------------------------------------------------------------------------
__global__ __launch_bounds__(256) void k_gemm(const float* __restrict__ x,
                                              const float* __restrict__ W) {
    __shared__ float Ws[32 * 256];
    __shared__ float xs[32 * 33];

    const int tid  = threadIdx.x;
    const int row0 = blockIdx.x * 32;
    const int ty   = tid >> 4;
    const int tx   = tid & 15;

    unsigned long long acc2[2][8];
#pragma unroll
    for (int r = 0; r < 2; r++)
#pragma unroll
        for (int c = 0; c < 8; c++) acc2[r][c] = 0ull;

    for (int kc = 0; kc < FIN; kc += 32) {
        __syncthreads();
        const float4* W4 = (const float4*)(W + kc * 256);
#pragma unroll
        for (int t = 0; t < 8; t++) {
            int idx = tid + 256 * t;
            ((float4*)Ws)[idx] = W4[idx];
        }
        {
            int r  = tid >> 3;
            int kq = tid & 7;
            float4 v = *(const float4*)(x + (size_t)(row0 + r) * FIN + kc + kq * 4);
            float* dst = &xs[r * 33 + kq * 4];
            dst[0] = v.x; dst[1] = v.y; dst[2] = v.z; dst[3] = v.w;
        }
        __syncthreads();
#pragma unroll
        for (int k = 0; k < 32; k++) {
            float x0 = xs[(ty * 2 + 0) * 33 + k];
            float x1 = xs[(ty * 2 + 1) * 33 + k];
            unsigned long long xp0 = pk2(x0, x0);
            unsigned long long xp1 = pk2(x1, x1);
#pragma unroll
            for (int c = 0; c < 8; c++) {
                unsigned long long wv =
                    *(const unsigned long long*)&Ws[k * 256 + tx * 2 + c * 32];
                fma2(acc2[0][c], xp0, wv);
                fma2(acc2[1][c], xp1, wv);
            }
        }
    }
#pragma unroll
    for (int r = 0; r < 2; r++) {
        int g = row0 + ty * 2 + r;
        int b = g / Nq;
        int n = g % Nq;
#pragma unroll
        for (int c = 0; c < 8; c++) {
            int o    = tx * 2 + c * 32;
            int head = o >> 6;
            int d    = o & 63;
            float2 v = upk(acc2[r][c]);
            *(float2*)&g_h[(((size_t)b * Hq + head) * Nq + n) * Dq + d] = v;
        }
    }
}

// ---------------------------------------------------------------------------
// Kernel 2: ei/ej per (b,head,n). One warp per row.
// ---------------------------------------------------------------------------
__global__ __launch_bounds__(256) void k_ev(const float* __restrict__ a) {
    int task = blockIdx.x * 8 + (threadIdx.x >> 5);
    int lane = threadIdx.x & 31;
    const float* hr = g_h + (size_t)task * Dq;
    float v0 = hr[lane], v1 = hr[lane + 32];
    float e1 = v0 * a[lane]      + v1 * a[lane + 32];
    float e2 = v0 * a[64 + lane] + v1 * a[96 + lane];
#pragma unroll
    for (int off = 16; off > 0; off >>= 1) {
        e1 += __shfl_down_sync(0xffffffffu, e1, off);
        e2 += __shfl_down_sync(0xffffffffu, e2, off);
    }
    if (lane == 0) {
        g_ei[task] = e1;
        g_ej[task] = e2;
    }
}

// dummy: keeps ncu's fixed capture slot on k_attn (4th launch)
__global__ void k_dummy() {
    if (threadIdx.x == 0 && blockIdx.x == 0) g_sink = 1;
}

// ---------------------------------------------------------------------------
// Kernel 3: GAT attention via mma.sync bf16, v2.
// num_i = e^{ei}(A.U)_i + e^{0.2ei}(B.L)_i ; den accumulated fp32 in build.
// Warp grid 4M x 2N, warp tile 32 rows x 32 cols. 64-j chunks, 4 k16 steps.
// ---------------------------------------------------------------------------
#define PITA 144    // A/B mask tile row pitch bytes (64 bf16 + pad)
#define PITU 144    // U/L tile row pitch bytes (64 bf16 + pad)
#define OFF_B   18432
#define OFF_UH  36864
#define OFF_UL  46080
#define OFF_LH  55296
#define OFF_LL  64512
#define OFF_X1  73728
#define OFF_X2  81920
#define OFF_EJ  90112
#define SMEM_AT 98304

__global__ __launch_bounds__(256, 2) void k_attn(const int* __restrict__ adj) {
    extern __shared__ char dyn[];
    __shared__ float ei_s[128];
    __shared__ float den1p[256], den2p[256];

    char*  Asm   = dyn;
    char*  Bsm   = dyn + OFF_B;
    char*  Uhm   = dyn + OFF_UH;
    char*  Ulm   = dyn + OFF_UL;
    char*  Lhm   = dyn + OFF_LH;
    char*  Llm   = dyn + OFF_LL;
    float* exj1f = (float*)(dyn + OFF_X1);
    float* exj2f = (float*)(dyn + OFF_X2);
    float* ejf   = (float*)(dyn + OFF_EJ);

    const int tid  = threadIdx.x;
    const int wid  = tid >> 5;
    const int lane = tid & 31;
    const int it   = blockIdx.x & 15;
    const int head = (blockIdx.x >> 4) & 3;
    const int b    = blockIdx.x >> 6;
    const int i0   = it * 128;
    const int bh   = b * Hq + head;
    // warp tile: 32 rows x 32 cols
    const int mg   = wid >> 1;
    const int ngrp = wid & 1;
    const int m0   = mg * 32;
    const int n0   = ngrp * 32;

    const float* Vg = g_h + (size_t)bh * Nq * Dq;

    // hoist: ej, exp(ej), exp(.2 ej) for all 2048 j; ei for this i-tile
#pragma unroll
    for (int t = 0; t < 8; t++) {
        int j = tid + 256 * t;
        float e = g_ej[bh * Nq + j];
        ejf[j]   = e;
        exj1f[j] = __expf(e);
        exj2f[j] = __expf(0.2f * e);
    }
    if (tid < 128) ei_s[tid] = g_ei[bh * Nq + i0 + tid];
    __syncthreads();

    const uint32_t AsU = s2u(Asm), BsU = s2u(Bsm);
    const uint32_t UhU = s2u(Uhm), UlU = s2u(Ulm);
    const uint32_t LhU = s2u(Lhm), LlU = s2u(Llm);
    const uint32_t aL = AsU + (uint32_t)(m0 + (lane & 15)) * PITA +
                        (uint32_t)(lane >> 4) * 16;
    const uint32_t bL = BsU + (uint32_t)(m0 + (lane & 15)) * PITA +
                        (uint32_t)(lane >> 4) * 16;
    const uint32_t uB = (uint32_t)(lane & 15) * PITU +
                        (uint32_t)(lane >> 4) * 16 + (uint32_t)n0 * 2;

    // build-phase thread mapping
    const int   mi   = tid >> 1;              // mask row 0..127
    const int   jh   = (tid & 1) * 32;        // mask j-half
    const float eIv  = ei_s[mi];
    const int*  ar0  = adj + ((size_t)b * Nq + i0 + mi) * Nq;
    const int   uj   = tid >> 2;              // U row 0..63
    const int   dq   = (tid & 3) * 16;        // d quarter

    float C1[2][4][4], C2[2][4][4];
#pragma unroll
    for (int mt = 0; mt < 2; mt++)
#pragma unroll
        for (int nt = 0; nt < 4; nt++)
#pragma unroll
            for (int q = 0; q < 4; q++) {
                C1[mt][nt][q] = 0.f;
                C2[mt][nt][q] = 0.f;
            }
    float dd1 = 0.f, dd2 = 0.f;

    for (int ch = 0; ch < 32; ch++) {
        const int j0 = ch * 64;
        __syncthreads();   // previous chunk's ldmatrix done

        // ---- masks A,B + fp32 den partials: thread owns row mi, 32 j ----
        {
            const int4* ap = (const int4*)(ar0 + j0 + jh);
#pragma unroll
            for (int q = 0; q < 8; q++) {
                int4 m = ap[q];
                int j  = jh + 4 * q;
                float s0 = eIv + ejf[j0 + j + 0];
                float s1 = eIv + ejf[j0 + j + 1];
                float s2 = eIv + ejf[j0 + j + 2];
                float s3 = eIv + ejf[j0 + j + 3];
                uint32_t a0 = (m.x && s0 >= 0.f) ? 0x3F80u : 0u;
                uint32_t a1 = (m.y && s1 >= 0.f) ? 0x3F80u : 0u;
                uint32_t a2 = (m.z && s2 >= 0.f) ? 0x3F80u : 0u;
                uint32_t a3 = (m.w && s3 >= 0.f) ? 0x3F80u : 0u;
                uint32_t b0 = (m.x && s0 < 0.f) ? 0x3F80u : 0u;
                uint32_t b1 = (m.y && s1 < 0.f) ? 0x3F80u : 0u;
                uint32_t b2 = (m.z && s2 < 0.f) ? 0x3F80u : 0u;
                uint32_t b3 = (m.w && s3 < 0.f) ? 0x3F80u : 0u;
                if (a0) dd1 += exj1f[j0 + j + 0];
                if (a1) dd1 += exj1f[j0 + j + 1];
                if (a2) dd1 += exj1f[j0 + j + 2];
                if (a3) dd1 += exj1f[j0 + j + 3];
                if (b0) dd2 += exj2f[j0 + j + 0];
                if (b1) dd2 += exj2f[j0 + j + 1];
                if (b2) dd2 += exj2f[j0 + j + 2];
                if (b3) dd2 += exj2f[j0 + j + 3];
                uint2 pa = make_uint2(a0 | (a1 << 16), a2 | (a3 << 16));
                uint2 pb = make_uint2(b0 | (b1 << 16), b2 | (b3 << 16));
                *(uint2*)(Asm + mi * PITA + j * 2) = pa;
                *(uint2*)(Bsm + mi * PITA + j * 2) = pb;
            }
        }

        // ---- U/L tiles: thread owns row uj (j), 16 d-cols ----
        {
            const float* vr = Vg + (size_t)(j0 + uj) * Dq + dq;
            float x1 = exj1f[j0 + uj];
            float x2 = exj2f[j0 + uj];
            float v[16];
#pragma unroll
            for (int g = 0; g < 4; g++) {
                float4 f = *(const float4*)(vr + 4 * g);
                v[4 * g] = f.x; v[4 * g + 1] = f.y;
                v[4 * g + 2] = f.z; v[4 * g + 3] = f.w;
            }
            uint32_t uh[8], ul[8], lh[8], ll[8];
#pragma unroll
            for (int g = 0; g < 8; g++) {
                float p0 = v[2 * g] * x1, p1 = v[2 * g + 1] * x1;
                float q0 = v[2 * g] * x2, q1 = v[2 * g + 1] * x2;
                float ph0 = __bfloat162float(__float2bfloat16(p0));
                float ph1 = __bfloat162float(__float2bfloat16(p1));
                float qh0 = __bfloat162float(__float2bfloat16(q0));
                float qh1 = __bfloat162float(__float2bfloat16(q1));
                uh[g] = pbf(ph0, ph1);
                ul[g] = pbf(p0 - ph0, p1 - ph1);
                lh[g] = pbf(qh0, qh1);
                ll[g] = pbf(q0 - qh0, q1 - qh1);
            }
            size_t rowo = (size_t)(uj * PITU + dq * 2);
            *(uint4*)(Uhm + rowo)      = *(uint4*)&uh[0];
            *(uint4*)(Uhm + rowo + 16) = *(uint4*)&uh[4];
            *(uint4*)(Ulm + rowo)      = *(uint4*)&ul[0];
            *(uint4*)(Ulm + rowo + 16) = *(uint4*)&ul[4];
            *(uint4*)(Lhm + rowo)      = *(uint4*)&lh[0];
            *(uint4*)(Lhm + rowo + 16) = *(uint4*)&lh[4];
            *(uint4*)(Llm + rowo)      = *(uint4*)&ll[0];
            *(uint4*)(Llm + rowo + 16) = *(uint4*)&ll[4];
        }
        __syncthreads();

        // ---- compute: 4 k16 steps, warp tile 32x32 ----
#pragma unroll
        for (int ks = 0; ks < 4; ks++) {
            uint32_t amA[2][4], amB[2][4];
            ldsm4(amA[0], aL + ks * 32);
            ldsm4(amA[1], aL + 16 * PITA + ks * 32);
            ldsm4(amB[0], bL + ks * 32);
            ldsm4(amB[1], bL + 16 * PITA + ks * 32);
            const uint32_t ub = uB + (uint32_t)(ks * 16 * PITU);
#pragma unroll
            for (int ng = 0; ng < 2; ng++) {
                uint32_t f[4];
                ldsm4t(f, UhU + ub + ng * 32);
                mmab(C1[0][2 * ng],     amA[0], f);
                mmab(C1[0][2 * ng + 1], amA[0], f + 2);
                mmab(C1[1][2 * ng],     amA[1], f);
                mmab(C1[1][2 * ng + 1], amA[1], f + 2);
                ldsm4t(f, UlU + ub + ng * 32);
                mmab(C1[0][2 * ng],     amA[0], f);
                mmab(C1[0][2 * ng + 1], amA[0], f + 2);
                mmab(C1[1][2 * ng],     amA[1], f);
                mmab(C1[1][2 * ng + 1], amA[1], f + 2);
                ldsm4t(f, LhU + ub + ng * 32);
                mmab(C2[0][2 * ng],     amB[0], f);
                mmab(C2[0][2 * ng + 1], amB[0], f + 2);
                mmab(C2[1][2 * ng],     amB[1], f);
                mmab(C2[1][2 * ng + 1], amB[1], f + 2);
                ldsm4t(f, LlU + ub + ng * 32);
                mmab(C2[0][2 * ng],     amB[0], f);
                mmab(C2[0][2 * ng + 1], amB[0], f + 2);
                mmab(C2[1][2 * ng],     amB[1], f);
                mmab(C2[1][2 * ng + 1], amB[1], f + 2);
            }
        }
    }

    den1p[tid] = dd1;
    den2p[tid] = dd2;
    __syncthreads();

    // ---- readout ----
    const int r0 = lane >> 2;
    const int c0 = (lane & 3) * 2;
#pragma unroll
    for (int mt = 0; mt < 2; mt++) {
#pragma unroll
        for (int half = 0; half < 2; half++) {
            int row = m0 + mt * 16 + r0 + half * 8;
            float sA = __expf(ei_s[row]);
            float sB = __expf(0.2f * ei_s[row]);
            float den = sA * (den1p[2 * row] + den1p[2 * row + 1]) +
                        sB * (den2p[2 * row] + den2p[2 * row + 1]);
            float inv = 1.f / den;
            float* og = g_o + ((size_t)bh * Nq + i0 + row) * Dq;
#pragma unroll
            for (int nt = 0; nt < 4; nt++) {
                float2 o;
                o.x = (sA * C1[mt][nt][2 * half] + sB * C2[mt][nt][2 * half]) * inv;
                o.y = (sA * C1[mt][nt][2 * half + 1] +
                       sB * C2[mt][nt][2 * half + 1]) * inv;
                *(float2*)&og[n0 + nt * 8 + c0] = o;
            }
        }
    }
}

// ---------------------------------------------------------------------------
// Kernel 5: out[b][n][d] = mean over heads of g_o
// ---------------------------------------------------------------------------
__global__ __launch_bounds__(256) void k_mean(float* __restrict__ out) {
    int idx = blockIdx.x * 256 + threadIdx.x;
    if (idx >= Bq * Nq * Dq) return;
    int d = idx & 63;
    int n = (idx >> 6) & (Nq - 1);
    int b = idx >> 17;
    float s = 0.f;
#pragma unroll
    for (int h = 0; h < Hq; h++)
        s += g_o[(((size_t)b * Hq + h) * Nq + n) * Dq + d];
    out[idx] = 0.25f * s;
}

// ---------------------------------------------------------------------------
extern "C" void kernel_launch(void* const* d_in, const int* in_sizes, int n_in,
                              void* d_out, int out_size) {
    const float* x   = (const float*)d_in[0];
    const int*   adj = (const int*)  d_in[1];
    const float* W   = (const float*)d_in[2];
    const float* a   = (const float*)d_in[3];
    float*       out = (float*)d_out;

    cudaFuncSetAttribute(k_attn, cudaFuncAttributeMaxDynamicSharedMemorySize,
                         SMEM_AT);

    k_gemm <<<(Bq * Nq) / 32, 256>>>(x, W);
    k_ev   <<<(Bq * Hq * Nq) / 8, 256>>>(a);
    k_dummy<<<1, 32>>>();
    k_attn <<<Bq * Hq * (Nq / 128), 256, SMEM_AT>>>(adj);
    k_mean <<<(Bq * Nq * Dq + 255) / 256, 256>>>(out);
}

// round 12
// speedup vs baseline: 1.4889x; 1.4889x over previous
#include <cuda_runtime.h>
#include <cuda_bf16.h>
#include <cstdint>

// Problem constants
#define Bq   4
#define Nq   2048
#define FIN  128
#define Hq   4
#define Dq   64
#define ALPHA 0.2f

// Scratch
__device__ float g_h[Bq * Hq * Nq * Dq];    // [bh][n][d] (8 MB)
__device__ float g_o[Bq * Hq * Nq * Dq];
__device__ float g_ei[Bq * Hq * Nq];
__device__ float g_ej[Bq * Hq * Nq];
__device__ int   g_sink;

// ---- packed f32x2 helpers (k_gemm) ----------------------------------------
__device__ __forceinline__ unsigned long long pk2(float lo, float hi) {
    unsigned long long r;
    asm("mov.b64 %0, {%1,%2};" : "=l"(r) : "f"(lo), "f"(hi));
    return r;
}
__device__ __forceinline__ void fma2(unsigned long long& d,
                                     unsigned long long a,
                                     unsigned long long b) {
    asm("fma.rn.f32x2 %0, %1, %2, %0;" : "+l"(d) : "l"(a), "l"(b));
}
__device__ __forceinline__ float2 upk(unsigned long long v) {
    float2 f;
    asm("mov.b64 {%0,%1}, %2;" : "=f"(f.x), "=f"(f.y) : "l"(v));
    return f;
}

// ---- mma.sync helpers -----------------------------------------------------
__device__ __forceinline__ uint32_t s2u(const void* p) {
    uint32_t a;
    asm("{ .reg .u64 t; cvta.to.shared.u64 t, %1; cvt.u32.u64 %0, t; }"
        : "=r"(a) : "l"(p));
    return a;
}
__device__ __forceinline__ void ldsm4(uint32_t* r, uint32_t a) {
    asm volatile("ldmatrix.sync.aligned.m8n8.x4.shared.b16 {%0,%1,%2,%3},[%4];"
                 : "=r"(r[0]), "=r"(r[1]), "=r"(r[2]), "=r"(r[3]) : "r"(a));
}
__device__ __forceinline__ void ldsm4t(uint32_t* r, uint32_t a) {
    asm volatile(
        "ldmatrix.sync.aligned.m8n8.x4.trans.shared.b16 {%0,%1,%2,%3},[%4];"
        : "=r"(r[0]), "=r"(r[1]), "=r"(r[2]), "=r"(r[3]) : "r"(a));
}
__device__ __forceinline__ void ldsm2t(uint32_t* r, uint32_t a) {
    asm volatile(
        "ldmatrix.sync.aligned.m8n8.x2.trans.shared.b16 {%0,%1},[%2];"
        : "=r"(r[0]), "=r"(r[1]) : "r"(a));
}
__device__ __forceinline__ void mmab(float* c, const uint32_t* a,
                                     const uint32_t* b) {
    asm volatile(
        "mma.sync.aligned.m16n8k16.row.col.f32.bf16.bf16.f32 "
        "{%0,%1,%2,%3},{%4,%5,%6,%7},{%8,%9},{%0,%1,%2,%3};"
        : "+f"(c[0]), "+f"(c[1]), "+f"(c[2]), "+f"(c[3])
        : "r"(a[0]), "r"(a[1]), "r"(a[2]), "r"(a[3]), "r"(b[0]), "r"(b[1]));
}
__device__ __forceinline__ uint32_t pbf(float x, float y) {
    __nv_bfloat162 t = __floats2bfloat162_rn(x, y);
    return *(uint32_t*)&t;
}

// ---------------------------------------------------------------------------
// Kernel 1: h = x @ W -> g_h[b][head][n][d]
// ---------------------------------------------------------------------------
__global__ __launch_bounds__(256) void k_gemm(const float* __restrict__ x,
                                              const float* __restrict__ W) {
    __shared__ float Ws[32 * 256];
    __shared__ float xs[32 * 33];

    const int tid  = threadIdx.x;
    const int row0 = blockIdx.x * 32;
    const int ty   = tid >> 4;
    const int tx   = tid & 15;

    unsigned long long acc2[2][8];
#pragma unroll
    for (int r = 0; r < 2; r++)
#pragma unroll
        for (int c = 0; c < 8; c++) acc2[r][c] = 0ull;

    for (int kc = 0; kc < FIN; kc += 32) {
        __syncthreads();
        const float4* W4 = (const float4*)(W + kc * 256);
#pragma unroll
        for (int t = 0; t < 8; t++) {
            int idx = tid + 256 * t;
            ((float4*)Ws)[idx] = W4[idx];
        }
        {
            int r  = tid >> 3;
            int kq = tid & 7;
            float4 v = *(const float4*)(x + (size_t)(row0 + r) * FIN + kc + kq * 4);
            float* dst = &xs[r * 33 + kq * 4];
            dst[0] = v.x; dst[1] = v.y; dst[2] = v.z; dst[3] = v.w;
        }
        __syncthreads();
#pragma unroll
        for (int k = 0; k < 32; k++) {
            float x0 = xs[(ty * 2 + 0) * 33 + k];
            float x1 = xs[(ty * 2 + 1) * 33 + k];
            unsigned long long xp0 = pk2(x0, x0);
            unsigned long long xp1 = pk2(x1, x1);
#pragma unroll
            for (int c = 0; c < 8; c++) {
                unsigned long long wv =
                    *(const unsigned long long*)&Ws[k * 256 + tx * 2 + c * 32];
                fma2(acc2[0][c], xp0, wv);
                fma2(acc2[1][c], xp1, wv);
            }
        }
    }
#pragma unroll
    for (int r = 0; r < 2; r++) {
        int g = row0 + ty * 2 + r;
        int b = g / Nq;
        int n = g % Nq;
#pragma unroll
        for (int c = 0; c < 8; c++) {
            int o    = tx * 2 + c * 32;
            int head = o >> 6;
            int d    = o & 63;
            float2 v = upk(acc2[r][c]);
            *(float2*)&g_h[(((size_t)b * Hq + head) * Nq + n) * Dq + d] = v;
        }
    }
}

// ---------------------------------------------------------------------------
// Kernel 2: ei/ej per (b,head,n). One warp per row.
// ---------------------------------------------------------------------------
__global__ __launch_bounds__(256) void k_ev(const float* __restrict__ a) {
    int task = blockIdx.x * 8 + (threadIdx.x >> 5);
    int lane = threadIdx.x & 31;
    const float* hr = g_h + (size_t)task * Dq;
    float v0 = hr[lane], v1 = hr[lane + 32];
    float e1 = v0 * a[lane]      + v1 * a[lane + 32];
    float e2 = v0 * a[64 + lane] + v1 * a[96 + lane];
#pragma unroll
    for (int off = 16; off > 0; off >>= 1) {
        e1 += __shfl_down_sync(0xffffffffu, e1, off);
        e2 += __shfl_down_sync(0xffffffffu, e2, off);
    }
    if (lane == 0) {
        g_ei[task] = e1;
        g_ej[task] = e2;
    }
}

// dummy: keeps ncu's fixed capture slot on k_attn (4th launch)
__global__ void k_dummy() {
    if (threadIdx.x == 0 && blockIdx.x == 0) g_sink = 1;
}

// ---------------------------------------------------------------------------
// Kernel 3: GAT attention via mma.sync bf16, v3.
// R10 structure (den as MMA column 64, branch-free build, PITU=176) +
// 4M x 2N warp grid (warp tile 32 rows x 32 cols; den tile on ngrp=1 warps,
// staged through smem for readout).
// ---------------------------------------------------------------------------
#define PITA 144    // A/B mask tile row pitch bytes (64 bf16 + 8 pad)
#define PITU 176    // U/L tile row pitch bytes (72 bf16 data + 16 pad)
#define OFF_B   18432
#define OFF_UH  36864
#define OFF_UL  48128
#define OFF_LH  59392
#define OFF_LL  70656
#define OFF_X1  81920
#define OFF_X2  90112
#define OFF_EJ  98304
#define SMEM_AT 106496

__global__ __launch_bounds__(256, 2) void k_attn(const int* __restrict__ adj) {
    extern __shared__ char dyn[];
    __shared__ float ei_s[128];
    __shared__ float dns1[128], dns2[128];

    char*  Asm   = dyn;
    char*  Bsm   = dyn + OFF_B;
    char*  Uhm   = dyn + OFF_UH;
    char*  Ulm   = dyn + OFF_UL;
    char*  Lhm   = dyn + OFF_LH;
    char*  Llm   = dyn + OFF_LL;
    float* exj1f = (float*)(dyn + OFF_X1);
    float* exj2f = (float*)(dyn + OFF_X2);
    float* ejf   = (float*)(dyn + OFF_EJ);

    const int tid  = threadIdx.x;
    const int wid  = tid >> 5;
    const int lane = tid & 31;
    const int it   = blockIdx.x & 15;
    const int head = (blockIdx.x >> 4) & 3;
    const int b    = blockIdx.x >> 6;
    const int i0   = it * 128;
    const int bh   = b * Hq + head;
    // warp grid: 4 m-groups x 2 n-groups; warp tile 32 rows x 32 cols
    const int mg   = wid >> 1;
    const int ngrp = wid & 1;
    const int m0   = mg * 32;
    const int n0   = ngrp * 32;

    const float* Vg = g_h + (size_t)bh * Nq * Dq;

    // hoist: ej, exp(ej), exp(.2 ej) for all 2048 j; ei for this i-tile
#pragma unroll
    for (int t = 0; t < 8; t++) {
        int j = tid + 256 * t;
        float e = g_ej[bh * Nq + j];
        ejf[j]   = e;
        exj1f[j] = __expf(e);
        exj2f[j] = __expf(0.2f * e);
    }
    if (tid < 128) ei_s[tid] = g_ei[bh * Nq + i0 + tid];
    __syncthreads();

    const uint32_t AsU = s2u(Asm), BsU = s2u(Bsm);
    const uint32_t UhU = s2u(Uhm), UlU = s2u(Ulm);
    const uint32_t LhU = s2u(Lhm), LlU = s2u(Llm);
    const uint32_t aL = AsU + (uint32_t)(m0 + (lane & 15)) * PITA +
                        (uint32_t)(lane >> 4) * 16;
    const uint32_t bL = BsU + (uint32_t)(m0 + (lane & 15)) * PITA +
                        (uint32_t)(lane >> 4) * 16;
    const uint32_t uB = (uint32_t)(lane & 15) * PITU +
                        (uint32_t)(lane >> 4) * 16 + (uint32_t)n0 * 2;
    const uint32_t uD = (uint32_t)(lane & 15) * PITU + 128;  // den col 64

    // build-phase thread mapping
    const int   mi   = tid >> 1;              // mask row 0..127
    const int   jh   = (tid & 1) * 32;        // mask j-half
    const float eIv  = ei_s[mi];
    const int*  ar0  = adj + ((size_t)b * Nq + i0 + mi) * Nq;
    const int   uj   = tid >> 2;              // U row 0..63
    const int   dq   = (tid & 3) * 16;        // d quarter

    float C1[2][4][4], C2[2][4][4];
    float C1d[2][4], C2d[2][4];
#pragma unroll
    for (int mt = 0; mt < 2; mt++) {
#pragma unroll
        for (int nt = 0; nt < 4; nt++)
#pragma unroll
            for (int q = 0; q < 4; q++) {
                C1[mt][nt][q] = 0.f;
                C2[mt][nt][q] = 0.f;
            }
#pragma unroll
        for (int q = 0; q < 4; q++) { C1d[mt][q] = 0.f; C2d[mt][q] = 0.f; }
    }

    for (int ch = 0; ch < 32; ch++) {
        const int j0 = ch * 64;
        __syncthreads();   // previous chunk's ldmatrix done

        // ---- masks A,B: thread owns row mi, 32 j (branch-free) ----
        {
            const int4* ap = (const int4*)(ar0 + j0 + jh);
#pragma unroll
            for (int q = 0; q < 8; q++) {
                int4 m = ap[q];
                int j  = jh + 4 * q;
                float s0 = eIv + ejf[j0 + j + 0];
                float s1 = eIv + ejf[j0 + j + 1];
                float s2 = eIv + ejf[j0 + j + 2];
                float s3 = eIv + ejf[j0 + j + 3];
                uint32_t a0 = (m.x && s0 >= 0.f) ? 0x3F80u : 0u;
                uint32_t a1 = (m.y && s1 >= 0.f) ? 0x3F80u : 0u;
                uint32_t a2 = (m.z && s2 >= 0.f) ? 0x3F80u : 0u;
                uint32_t a3 = (m.w && s3 >= 0.f) ? 0x3F80u : 0u;
                uint32_t b0 = (m.x && s0 < 0.f) ? 0x3F80u : 0u;
                uint32_t b1 = (m.y && s1 < 0.f) ? 0x3F80u : 0u;
                uint32_t b2 = (m.z && s2 < 0.f) ? 0x3F80u : 0u;
                uint32_t b3 = (m.w && s3 < 0.f) ? 0x3F80u : 0u;
                uint2 pa = make_uint2(a0 | (a1 << 16), a2 | (a3 << 16));
                uint2 pb = make_uint2(b0 | (b1 << 16), b2 | (b3 << 16));
                *(uint2*)(Asm + mi * PITA + j * 2) = pa;
                *(uint2*)(Bsm + mi * PITA + j * 2) = pb;
            }
        }

        // ---- U/L tiles: thread owns row uj (j), 16 d-cols ----
        {
            const float* vr = Vg + (size_t)(j0 + uj) * Dq + dq;
            float x1 = exj1f[j0 + uj];
            float x2 = exj2f[j0 + uj];
            float v[16];
#pragma unroll
            for (int g = 0; g < 4; g++) {
                float4 f = *(const float4*)(vr + 4 * g);
                v[4 * g] = f.x; v[4 * g + 1] = f.y;
                v[4 * g + 2] = f.z; v[4 * g + 3] = f.w;
            }
            uint32_t uh[8], ul[8], lh[8], ll[8];
#pragma unroll
            for (int g = 0; g < 8; g++) {
                float p0 = v[2 * g] * x1, p1 = v[2 * g + 1] * x1;
                float q0 = v[2 * g] * x2, q1 = v[2 * g + 1] * x2;
                float ph0 = __bfloat162float(__float2bfloat16(p0));
                float ph1 = __bfloat162float(__float2bfloat16(p1));
                float qh0 = __bfloat162float(__float2bfloat16(q0));
                float qh1 = __bfloat162float(__float2bfloat16(q1));
                uh[g] = pbf(ph0, ph1);
                ul[g] = pbf(p0 - ph0, p1 - ph1);
                lh[g] = pbf(qh0, qh1);
                ll[g] = pbf(q0 - qh0, q1 - qh1);
            }
            size_t rowo = (size_t)(uj * PITU + dq * 2);
            *(uint4*)(Uhm + rowo)      = *(uint4*)&uh[0];
            *(uint4*)(Uhm + rowo + 16) = *(uint4*)&uh[4];
            *(uint4*)(Ulm + rowo)      = *(uint4*)&ul[0];
            *(uint4*)(Ulm + rowo + 16) = *(uint4*)&ul[4];
            *(uint4*)(Lhm + rowo)      = *(uint4*)&lh[0];
            *(uint4*)(Lhm + rowo + 16) = *(uint4*)&lh[4];
            *(uint4*)(Llm + rowo)      = *(uint4*)&ll[0];
            *(uint4*)(Llm + rowo + 16) = *(uint4*)&ll[4];
            if ((tid & 3) == 3) {   // den column 64 (+ zeros 65-71)
                float h1 = __bfloat162float(__float2bfloat16(x1));
                float h2 = __bfloat162float(__float2bfloat16(x2));
                size_t doff = (size_t)(uj * PITU + 128);
                *(uint4*)(Uhm + doff) = make_uint4(pbf(h1, 0.f), 0, 0, 0);
                *(uint4*)(Ulm + doff) = make_uint4(pbf(x1 - h1, 0.f), 0, 0, 0);
                *(uint4*)(Lhm + doff) = make_uint4(pbf(h2, 0.f), 0, 0, 0);
                *(uint4*)(Llm + doff) = make_uint4(pbf(x2 - h2, 0.f), 0, 0, 0);
            }
        }
        __syncthreads();

        // ---- compute: 4 k16 steps, warp tile 32x32 (+den on ngrp1) ----
#pragma unroll
        for (int ks = 0; ks < 4; ks++) {
            uint32_t amA[2][4], amB[2][4];
            ldsm4(amA[0], aL + ks * 32);
            ldsm4(amA[1], aL + 16 * PITA + ks * 32);
            ldsm4(amB[0], bL + ks * 32);
            ldsm4(amB[1], bL + 16 * PITA + ks * 32);
            const uint32_t ub = uB + (uint32_t)(ks * 16 * PITU);
#pragma unroll
            for (int ng = 0; ng < 2; ng++) {
                uint32_t f[4];
                ldsm4t(f, UhU + ub + ng * 32);
                mmab(C1[0][2 * ng],     amA[0], f);
                mmab(C1[0][2 * ng + 1], amA[0], f + 2);
                mmab(C1[1][2 * ng],     amA[1], f);
                mmab(C1[1][2 * ng + 1], amA[1], f + 2);
                ldsm4t(f, UlU + ub + ng * 32);
                mmab(C1[0][2 * ng],     amA[0], f);
                mmab(C1[0][2 * ng + 1], amA[0], f + 2);
                mmab(C1[1][2 * ng],     amA[1], f);
                mmab(C1[1][2 * ng + 1], amA[1], f + 2);
                ldsm4t(f, LhU + ub + ng * 32);
                mmab(C2[0][2 * ng],     amB[0], f);
                mmab(C2[0][2 * ng + 1], amB[0], f + 2);
                mmab(C2[1][2 * ng],     amB[1], f);
                mmab(C2[1][2 * ng + 1], amB[1], f + 2);
                ldsm4t(f, LlU + ub + ng * 32);
                mmab(C2[0][2 * ng],     amB[0], f);
                mmab(C2[0][2 * ng + 1], amB[0], f + 2);
                mmab(C2[1][2 * ng],     amB[1], f);
                mmab(C2[1][2 * ng + 1], amB[1], f + 2);
            }
            if (ngrp) {   // den tile (col 64), warp-uniform branch
                const uint32_t ud = uD + (uint32_t)(ks * 16 * PITU);
                uint32_t t0[2];
                ldsm2t(t0, UhU + ud);
                mmab(C1d[0], amA[0], t0); mmab(C1d[1], amA[1], t0);
                ldsm2t(t0, UlU + ud);
                mmab(C1d[0], amA[0], t0); mmab(C1d[1], amA[1], t0);
                ldsm2t(t0, LhU + ud);
                mmab(C2d[0], amB[0], t0); mmab(C2d[1], amB[1], t0);
                ldsm2t(t0, LlU + ud);
                mmab(C2d[0], amB[0], t0); mmab(C2d[1], amB[1], t0);
            }
        }
    }

    // ---- stage den through smem ----
    if (ngrp && (lane & 3) == 0) {
        int r0 = lane >> 2;   // 0..7
#pragma unroll
        for (int mt = 0; mt < 2; mt++) {
            dns1[m0 + mt * 16 + r0]     = C1d[mt][0];
            dns2[m0 + mt * 16 + r0]     = C2d[mt][0];
            dns1[m0 + mt * 16 + r0 + 8] = C1d[mt][2];
            dns2[m0 + mt * 16 + r0 + 8] = C2d[mt][2];
        }
    }
    __syncthreads();

    // ---- readout ----
    const int r0 = lane >> 2;
    const int c0 = (lane & 3) * 2;
#pragma unroll
    for (int mt = 0; mt < 2; mt++) {
#pragma unroll
        for (int half = 0; half < 2; half++) {
            int row = m0 + mt * 16 + r0 + half * 8;
            float sA = __expf(ei_s[row]);
            float sB = __expf(0.2f * ei_s[row]);
            float den = sA * dns1[row] + sB * dns2[row];
            float inv = 1.f / den;
            float* og = g_o + ((size_t)bh * Nq + i0 + row) * Dq;
#pragma unroll
            for (int nt = 0; nt < 4; nt++) {
                float2 o;
                o.x = (sA * C1[mt][nt][2 * half] + sB * C2[mt][nt][2 * half]) * inv;
                o.y = (sA * C1[mt][nt][2 * half + 1] +
                       sB * C2[mt][nt][2 * half + 1]) * inv;
                *(float2*)&og[n0 + nt * 8 + c0] = o;
            }
        }
    }
}

// ---------------------------------------------------------------------------
// Kernel 5: out[b][n][d] = mean over heads of g_o
// ---------------------------------------------------------------------------
__global__ __launch_bounds__(256) void k_mean(float* __restrict__ out) {
    int idx = blockIdx.x * 256 + threadIdx.x;
    if (idx >= Bq * Nq * Dq) return;
    int d = idx & 63;
    int n = (idx >> 6) & (Nq - 1);
    int b = idx >> 17;
    float s = 0.f;
#pragma unroll
    for (int h = 0; h < Hq; h++)
        s += g_o[(((size_t)b * Hq + h) * Nq + n) * Dq + d];
    out[idx] = 0.25f * s;
}

// ---------------------------------------------------------------------------
extern "C" void kernel_launch(void* const* d_in, const int* in_sizes, int n_in,
                              void* d_out, int out_size) {
    const float* x   = (const float*)d_in[0];
    const int*   adj = (const int*)  d_in[1];
    const float* W   = (const float*)d_in[2];
    const float* a   = (const float*)d_in[3];
    float*       out = (float*)d_out;

    cudaFuncSetAttribute(k_attn, cudaFuncAttributeMaxDynamicSharedMemorySize,
                         SMEM_AT);

    k_gemm <<<(Bq * Nq) / 32, 256>>>(x, W);
    k_ev   <<<(Bq * Hq * Nq) / 8, 256>>>(a);
    k_dummy<<<1, 32>>>();
    k_attn <<<Bq * Hq * (Nq / 128), 256, SMEM_AT>>>(adj);
    k_mean <<<(Bq * Nq * Dq + 255) / 256, 256>>>(out);
}

// round 14
// speedup vs baseline: 1.5120x; 1.0155x over previous
#include <cuda_runtime.h>
#include <cuda_bf16.h>
#include <cstdint>

// Problem constants
#define Bq   4
#define Nq   2048
#define FIN  128
#define Hq   4
#define Dq   64
#define ALPHA 0.2f

// Scratch
__device__ float g_h[Bq * Hq * Nq * Dq];    // [bh][n][d] (8 MB)
__device__ float g_o[Bq * Hq * Nq * Dq];
__device__ float g_ei[Bq * Hq * Nq];
__device__ float g_ej[Bq * Hq * Nq];
// U/L tiles: 4 arrays [bh][2048][72] bf16 (cols 0-63 data, 64 den, 65-71 zero)
#define ULSTRIDE 2359296ull   // 16*2048*72
__device__ uint16_t g_ul[4 * ULSTRIDE];

// ---- packed f32x2 helpers (k_gemm) ----------------------------------------
__device__ __forceinline__ unsigned long long pk2(float lo, float hi) {
    unsigned long long r;
    asm("mov.b64 %0, {%1,%2};" : "=l"(r) : "f"(lo), "f"(hi));
    return r;
}
__device__ __forceinline__ void fma2(unsigned long long& d,
                                     unsigned long long a,
                                     unsigned long long b) {
    asm("fma.rn.f32x2 %0, %1, %2, %0;" : "+l"(d) : "l"(a), "l"(b));
}
__device__ __forceinline__ float2 upk(unsigned long long v) {
    float2 f;
    asm("mov.b64 {%0,%1}, %2;" : "=f"(f.x), "=f"(f.y) : "l"(v));
    return f;
}

// ---- mma.sync helpers -----------------------------------------------------
__device__ __forceinline__ uint32_t s2u(const void* p) {
    uint32_t a;
    asm("{ .reg .u64 t; cvta.to.shared.u64 t, %1; cvt.u32.u64 %0, t; }"
        : "=r"(a) : "l"(p));
    return a;
}
__device__ __forceinline__ void ldsm4(uint32_t* r, uint32_t a) {
    asm volatile("ldmatrix.sync.aligned.m8n8.x4.shared.b16 {%0,%1,%2,%3},[%4];"
                 : "=r"(r[0]), "=r"(r[1]), "=r"(r[2]), "=r"(r[3]) : "r"(a));
}
__device__ __forceinline__ void ldsm4t(uint32_t* r, uint32_t a) {
    asm volatile(
        "ldmatrix.sync.aligned.m8n8.x4.trans.shared.b16 {%0,%1,%2,%3},[%4];"
        : "=r"(r[0]), "=r"(r[1]), "=r"(r[2]), "=r"(r[3]) : "r"(a));
}
__device__ __forceinline__ void ldsm2t(uint32_t* r, uint32_t a) {
    asm volatile(
        "ldmatrix.sync.aligned.m8n8.x2.trans.shared.b16 {%0,%1},[%2];"
        : "=r"(r[0]), "=r"(r[1]) : "r"(a));
}
__device__ __forceinline__ void mmab(float* c, const uint32_t* a,
                                     const uint32_t* b) {
    asm volatile(
        "mma.sync.aligned.m16n8k16.row.col.f32.bf16.bf16.f32 "
        "{%0,%1,%2,%3},{%4,%5,%6,%7},{%8,%9},{%0,%1,%2,%3};"
        : "+f"(c[0]), "+f"(c[1]), "+f"(c[2]), "+f"(c[3])
        : "r"(a[0]), "r"(a[1]), "r"(a[2]), "r"(a[3]), "r"(b[0]), "r"(b[1]));
}
__device__ __forceinline__ uint32_t pbf(float x, float y) {
    __nv_bfloat162 t = __floats2bfloat162_rn(x, y);
    return *(uint32_t*)&t;
}

// ---------------------------------------------------------------------------
// Kernel 1: h = x @ W -> g_h[b][head][n][d]
// ---------------------------------------------------------------------------
__global__ __launch_bounds__(256) void k_gemm(const float* __restrict__ x,
                                              const float* __restrict__ W) {
    __shared__ float Ws[32 * 256];
    __shared__ float xs[32 * 33];

    const int tid  = threadIdx.x;
    const int row0 = blockIdx.x * 32;
    const int ty   = tid >> 4;
    const int tx   = tid & 15;

    unsigned long long acc2[2][8];
#pragma unroll
    for (int r = 0; r < 2; r++)
#pragma unroll
        for (int c = 0; c < 8; c++) acc2[r][c] = 0ull;

    for (int kc = 0; kc < FIN; kc += 32) {
        __syncthreads();
        const float4* W4 = (const float4*)(W + kc * 256);
#pragma unroll
        for (int t = 0; t < 8; t++) {
            int idx = tid + 256 * t;
            ((float4*)Ws)[idx] = W4[idx];
        }
        {
            int r  = tid >> 3;
            int kq = tid & 7;
            float4 v = *(const float4*)(x + (size_t)(row0 + r) * FIN + kc + kq * 4);
            float* dst = &xs[r * 33 + kq * 4];
            dst[0] = v.x; dst[1] = v.y; dst[2] = v.z; dst[3] = v.w;
        }
        __syncthreads();
#pragma unroll
        for (int k = 0; k < 32; k++) {
            float x0 = xs[(ty * 2 + 0) * 33 + k];
            float x1 = xs[(ty * 2 + 1) * 33 + k];
            unsigned long long xp0 = pk2(x0, x0);
            unsigned long long xp1 = pk2(x1, x1);
#pragma unroll
            for (int c = 0; c < 8; c++) {
                unsigned long long wv =
                    *(const unsigned long long*)&Ws[k * 256 + tx * 2 + c * 32];
                fma2(acc2[0][c], xp0, wv);
                fma2(acc2[1][c], xp1, wv);
            }
        }
    }
#pragma unroll
    for (int r = 0; r < 2; r++) {
        int g = row0 + ty * 2 + r;
        int b = g / Nq;
        int n = g % Nq;
#pragma unroll
        for (int c = 0; c < 8; c++) {
            int o    = tx * 2 + c * 32;
            int head = o >> 6;
            int d    = o & 63;
            float2 v = upk(acc2[r][c]);
            *(float2*)&g_h[(((size_t)b * Hq + head) * Nq + n) * Dq + d] = v;
        }
    }
}

// ---------------------------------------------------------------------------
// Kernel 2: ei/ej per (b,head,n). One warp per row.
// ---------------------------------------------------------------------------
__global__ __launch_bounds__(256) void k_ev(const float* __restrict__ a) {
    int task = blockIdx.x * 8 + (threadIdx.x >> 5);
    int lane = threadIdx.x & 31;
    const float* hr = g_h + (size_t)task * Dq;
    float v0 = hr[lane], v1 = hr[lane + 32];
    float e1 = v0 * a[lane]      + v1 * a[lane + 32];
    float e2 = v0 * a[64 + lane] + v1 * a[96 + lane];
#pragma unroll
    for (int off = 16; off > 0; off >>= 1) {
        e1 += __shfl_down_sync(0xffffffffu, e1, off);
        e2 += __shfl_down_sync(0xffffffffu, e2, off);
    }
    if (lane == 0) {
        g_ei[task] = e1;
        g_ej[task] = e2;
    }
}

// ---------------------------------------------------------------------------
// Kernel 3: k_prep — build U/L (bf16 hi/lo + den col) once per (bh, j).
// Thread = (bh, j, d-quarter). Grid 512 x 256.
// ---------------------------------------------------------------------------
__global__ __launch_bounds__(256) void k_prep() {
    int gidx = blockIdx.x * 256 + threadIdx.x;   // 16*2048*4
    int dq   = (gidx & 3) * 16;
    int j    = (gidx >> 2) & (Nq - 1);
    int bh   = gidx >> 13;

    float e  = g_ej[bh * Nq + j];
    float x1 = __expf(e);
    float x2 = __expf(0.2f * e);

    const float* vr = g_h + ((size_t)bh * Nq + j) * Dq + dq;
    float v[16];
#pragma unroll
    for (int g = 0; g < 4; g++) {
        float4 f = *(const float4*)(vr + 4 * g);
        v[4 * g] = f.x; v[4 * g + 1] = f.y;
        v[4 * g + 2] = f.z; v[4 * g + 3] = f.w;
    }
    uint32_t uh[8], ul[8], lh[8], ll[8];
#pragma unroll
    for (int g = 0; g < 8; g++) {
        float p0 = v[2 * g] * x1, p1 = v[2 * g + 1] * x1;
        float q0 = v[2 * g] * x2, q1 = v[2 * g + 1] * x2;
        float ph0 = __bfloat162float(__float2bfloat16(p0));
        float ph1 = __bfloat162float(__float2bfloat16(p1));
        float qh0 = __bfloat162float(__float2bfloat16(q0));
        float qh1 = __bfloat162float(__float2bfloat16(q1));
        uh[g] = pbf(ph0, ph1);
        ul[g] = pbf(p0 - ph0, p1 - ph1);
        lh[g] = pbf(qh0, qh1);
        ll[g] = pbf(q0 - qh0, q1 - qh1);
    }
    size_t row = ((size_t)bh * Nq + j) * 72;
    uint16_t* Uh = g_ul;
    uint16_t* Ul = g_ul + ULSTRIDE;
    uint16_t* Lh = g_ul + 2 * ULSTRIDE;
    uint16_t* Ll = g_ul + 3 * ULSTRIDE;
    *(uint4*)(Uh + row + dq)     = *(uint4*)&uh[0];
    *(uint4*)(Uh + row + dq + 8) = *(uint4*)&uh[4];
    *(uint4*)(Ul + row + dq)     = *(uint4*)&ul[0];
    *(uint4*)(Ul + row + dq + 8) = *(uint4*)&ul[4];
    *(uint4*)(Lh + row + dq)     = *(uint4*)&lh[0];
    *(uint4*)(Lh + row + dq + 8) = *(uint4*)&lh[4];
    *(uint4*)(Ll + row + dq)     = *(uint4*)&ll[0];
    *(uint4*)(Ll + row + dq + 8) = *(uint4*)&ll[4];
    if ((gidx & 3) == 3) {       // den column 64 (+ zeros 65-71)
        float h1 = __bfloat162float(__float2bfloat16(x1));
        float h2 = __bfloat162float(__float2bfloat16(x2));
        *(uint4*)(Uh + row + 64) = make_uint4(pbf(h1, 0.f), 0, 0, 0);
        *(uint4*)(Ul + row + 64) = make_uint4(pbf(x1 - h1, 0.f), 0, 0, 0);
        *(uint4*)(Lh + row + 64) = make_uint4(pbf(h2, 0.f), 0, 0, 0);
        *(uint4*)(Ll + row + 64) = make_uint4(pbf(x2 - h2, 0.f), 0, 0, 0);
    }
}

// ---------------------------------------------------------------------------
// Kernel 4: GAT attention via mma.sync bf16, v4.
// U/L tiles precomputed (k_prep) and fetched via cp.async, overlapped with
// the adj mask build. Compute phase identical to R12 (den col 64 in MMA).
// ---------------------------------------------------------------------------
#define PITA 144    // A/B mask tile row pitch bytes
#define PITU 144    // U/L tile row pitch bytes (72 bf16, no pad)
#define OFF_B   18432
#define OFF_UH  36864
#define OFF_UL  46080
#define OFF_LH  55296
#define OFF_LL  64512
#define OFF_EJ  73728
#define SMEM_AT 81920

__global__ __launch_bounds__(256, 2) void k_attn(const int* __restrict__ adj) {
    extern __shared__ char dyn[];
    __shared__ float ei_s[128];
    __shared__ float dns1[128], dns2[128];

    char*  Asm = dyn;
    char*  Bsm = dyn + OFF_B;
    char*  Uhm = dyn + OFF_UH;
    float* ejf = (float*)(dyn + OFF_EJ);

    const int tid  = threadIdx.x;
    const int wid  = tid >> 5;
    const int lane = tid & 31;
    const int it   = blockIdx.x & 15;
    const int head = (blockIdx.x >> 4) & 3;
    const int b    = blockIdx.x >> 6;
    const int i0   = it * 128;
    const int bh   = b * Hq + head;
    const int mg   = wid >> 1;
    const int ngrp = wid & 1;
    const int m0   = mg * 32;
    const int n0   = ngrp * 32;

    // hoist: ej for all 2048 j (mask signs); ei for this i-tile
#pragma unroll
    for (int t = 0; t < 8; t++) {
        int j = tid + 256 * t;
        ejf[j] = g_ej[bh * Nq + j];
    }
    if (tid < 128) ei_s[tid] = g_ei[bh * Nq + i0 + tid];
    __syncthreads();

    const uint32_t AsU = s2u(Asm), BsU = s2u(Bsm);
    const uint32_t UhU = s2u(Uhm);
    const uint32_t UlU = UhU + 9216, LhU = UhU + 18432, LlU = UhU + 27648;
    const uint32_t aL = AsU + (uint32_t)(m0 + (lane & 15)) * PITA +
                        (uint32_t)(lane >> 4) * 16;
    const uint32_t bL = BsU + (uint32_t)(m0 + (lane & 15)) * PITA +
                        (uint32_t)(lane >> 4) * 16;
    const uint32_t uB = (uint32_t)(lane & 15) * PITU +
                        (uint32_t)(lane >> 4) * 16 + (uint32_t)n0 * 2;
    const uint32_t uD = (uint32_t)(lane & 15) * PITU + 128;  // den col 64

    // build-phase thread mapping
    const int   mi   = tid >> 1;              // mask row 0..127
    const int   jh   = (tid & 1) * 32;        // mask j-half
    const float eIv  = ei_s[mi];
    const int*  ar0  = adj + ((size_t)b * Nq + i0 + mi) * Nq;
    // cp.async mapping: thread copies one U/L row (tile a, row r)
    const int   cpa  = tid >> 6;              // tile 0..3
    const int   cpr  = tid & 63;              // row 0..63
    const uint16_t* cpsrc0 = g_ul + (size_t)cpa * ULSTRIDE +
                             ((size_t)bh * Nq + cpr) * 72;
    const uint32_t  cpdst  = UhU + (uint32_t)cpa * 9216 + (uint32_t)cpr * PITU;

    float C1[2][4][4], C2[2][4][4];
    float C1d[2][4], C2d[2][4];
#pragma unroll
    for (int mt = 0; mt < 2; mt++) {
#pragma unroll
        for (int nt = 0; nt < 4; nt++)
#pragma unroll
            for (int q = 0; q < 4; q++) {
                C1[mt][nt][q] = 0.f;
                C2[mt][nt][q] = 0.f;
            }
#pragma unroll
        for (int q = 0; q < 4; q++) { C1d[mt][q] = 0.f; C2d[mt][q] = 0.f; }
    }

    for (int ch = 0; ch < 32; ch++) {
        const int j0 = ch * 64;
        __syncthreads();   // previous chunk's smem reads done

        // ---- prefetch U/L tiles (async, overlaps mask build) ----
        {
            const uint16_t* src = cpsrc0 + (size_t)j0 * 72;
#pragma unroll
            for (int seg = 0; seg < 9; seg++) {
                asm volatile("cp.async.ca.shared.global [%0], [%1], 16;"
                             :: "r"(cpdst + seg * 16), "l"(src + seg * 8)
                             : "memory");
            }
            asm volatile("cp.async.commit_group;" ::: "memory");
        }

        // ---- masks A,B: thread owns row mi, 32 j (branch-free) ----
        {
            const int4* ap = (const int4*)(ar0 + j0 + jh);
#pragma unroll
            for (int q = 0; q < 8; q++) {
                int4 m = ap[q];
                int j  = jh + 4 * q;
                float s0 = eIv + ejf[j0 + j + 0];
                float s1 = eIv + ejf[j0 + j + 1];
                float s2 = eIv + ejf[j0 + j + 2];
                float s3 = eIv + ejf[j0 + j + 3];
                uint32_t a0 = (m.x && s0 >= 0.f) ? 0x3F80u : 0u;
                uint32_t a1 = (m.y && s1 >= 0.f) ? 0x3F80u : 0u;
                uint32_t a2 = (m.z && s2 >= 0.f) ? 0x3F80u : 0u;
                uint32_t a3 = (m.w && s3 >= 0.f) ? 0x3F80u : 0u;
                uint32_t b0 = (m.x && s0 < 0.f) ? 0x3F80u : 0u;
                uint32_t b1 = (m.y && s1 < 0.f) ? 0x3F80u : 0u;
                uint32_t b2 = (m.z && s2 < 0.f) ? 0x3F80u : 0u;
                uint32_t b3 = (m.w && s3 < 0.f) ? 0x3F80u : 0u;
                uint2 pa = make_uint2(a0 | (a1 << 16), a2 | (a3 << 16));
                uint2 pb = make_uint2(b0 | (b1 << 16), b2 | (b3 << 16));
                *(uint2*)(Asm + mi * PITA + j * 2) = pa;
                *(uint2*)(Bsm + mi * PITA + j * 2) = pb;
            }
        }

        asm volatile("cp.async.wait_group 0;" ::: "memory");
        __syncthreads();

        // ---- compute: 4 k16 steps, warp tile 32x32 (+den on ngrp1) ----
#pragma unroll
        for (int ks = 0; ks < 4; ks++) {
            uint32_t amA[2][4], amB[2][4];
            ldsm4(amA[0], aL + ks * 32);
            ldsm4(amA[1], aL + 16 * PITA + ks * 32);
            ldsm4(amB[0], bL + ks * 32);
            ldsm4(amB[1], bL + 16 * PITA + ks * 32);
            const uint32_t ub = uB + (uint32_t)(ks * 16 * PITU);
#pragma unroll
            for (int ng = 0; ng < 2; ng++) {
                uint32_t f[4];
                ldsm4t(f, UhU + ub + ng * 32);
                mmab(C1[0][2 * ng],     amA[0], f);
                mmab(C1[0][2 * ng + 1], amA[0], f + 2);
                mmab(C1[1][2 * ng],     amA[1], f);
                mmab(C1[1][2 * ng + 1], amA[1], f + 2);
                ldsm4t(f, UlU + ub + ng * 32);
                mmab(C1[0][2 * ng],     amA[0], f);
                mmab(C1[0][2 * ng + 1], amA[0], f + 2);
                mmab(C1[1][2 * ng],     amA[1], f);
                mmab(C1[1][2 * ng + 1], amA[1], f + 2);
                ldsm4t(f, LhU + ub + ng * 32);
                mmab(C2[0][2 * ng],     amB[0], f);
                mmab(C2[0][2 * ng + 1], amB[0], f + 2);
                mmab(C2[1][2 * ng],     amB[1], f);
                mmab(C2[1][2 * ng + 1], amB[1], f + 2);
                ldsm4t(f, LlU + ub + ng * 32);
                mmab(C2[0][2 * ng],     amB[0], f);
                mmab(C2[0][2 * ng + 1], amB[0], f + 2);
                mmab(C2[1][2 * ng],     amB[1], f);
                mmab(C2[1][2 * ng + 1], amB[1], f + 2);
            }
            if (ngrp) {   // den tile (col 64), warp-uniform branch
                const uint32_t ud = uD + (uint32_t)(ks * 16 * PITU);
                uint32_t t0[2];
                ldsm2t(t0, UhU + ud);
                mmab(C1d[0], amA[0], t0); mmab(C1d[1], amA[1], t0);
                ldsm2t(t0, UlU + ud);
                mmab(C1d[0], amA[0], t0); mmab(C1d[1], amA[1], t0);
                ldsm2t(t0, LhU + ud);
                mmab(C2d[0], amB[0], t0); mmab(C2d[1], amB[1], t0);
                ldsm2t(t0, LlU + ud);
                mmab(C2d[0], amB[0], t0); mmab(C2d[1], amB[1], t0);
            }
        }
    }

    // ---- stage den through smem ----
    if (ngrp && (lane & 3) == 0) {
        int r0 = lane >> 2;
#pragma unroll
        for (int mt = 0; mt < 2; mt++) {
            dns1[m0 + mt * 16 + r0]     = C1d[mt][0];
            dns2[m0 + mt * 16 + r0]     = C2d[mt][0];
            dns1[m0 + mt * 16 + r0 + 8] = C1d[mt][2];
            dns2[m0 + mt * 16 + r0 + 8] = C2d[mt][2];
        }
    }
    __syncthreads();

    // ---- readout ----
    const int r0 = lane >> 2;
    const int c0 = (lane & 3) * 2;
#pragma unroll
    for (int mt = 0; mt < 2; mt++) {
#pragma unroll
        for (int half = 0; half < 2; half++) {
            int row = m0 + mt * 16 + r0 + half * 8;
            float sA = __expf(ei_s[row]);
            float sB = __expf(0.2f * ei_s[row]);
            float den = sA * dns1[row] + sB * dns2[row];
            float inv = 1.f / den;
            float* og = g_o + ((size_t)bh * Nq + i0 + row) * Dq;
#pragma unroll
            for (int nt = 0; nt < 4; nt++) {
                float2 o;
                o.x = (sA * C1[mt][nt][2 * half] + sB * C2[mt][nt][2 * half]) * inv;
                o.y = (sA * C1[mt][nt][2 * half + 1] +
                       sB * C2[mt][nt][2 * half + 1]) * inv;
                *(float2*)&og[n0 + nt * 8 + c0] = o;
            }
        }
    }
}

// ---------------------------------------------------------------------------
// Kernel 5: out[b][n][d] = mean over heads of g_o
// ---------------------------------------------------------------------------
__global__ __launch_bounds__(256) void k_mean(float* __restrict__ out) {
    int idx = blockIdx.x * 256 + threadIdx.x;
    if (idx >= Bq * Nq * Dq) return;
    int d = idx & 63;
    int n = (idx >> 6) & (Nq - 1);
    int b = idx >> 17;
    float s = 0.f;
#pragma unroll
    for (int h = 0; h < Hq; h++)
        s += g_o[(((size_t)b * Hq + h) * Nq + n) * Dq + d];
    out[idx] = 0.25f * s;
}

// ---------------------------------------------------------------------------
extern "C" void kernel_launch(void* const* d_in, const int* in_sizes, int n_in,
                              void* d_out, int out_size) {
    const float* x   = (const float*)d_in[0];
    const int*   adj = (const int*)  d_in[1];
    const float* W   = (const float*)d_in[2];
    const float* a   = (const float*)d_in[3];
    float*       out = (float*)d_out;

    cudaFuncSetAttribute(k_attn, cudaFuncAttributeMaxDynamicSharedMemorySize,
                         SMEM_AT);

    k_gemm<<<(Bq * Nq) / 32, 256>>>(x, W);
    k_ev  <<<(Bq * Hq * Nq) / 8, 256>>>(a);
    k_prep<<<(16 * Nq * 4) / 256, 256>>>();
    k_attn<<<Bq * Hq * (Nq / 128), 256, SMEM_AT>>>(adj);
    k_mean<<<(Bq * Nq * Dq + 255) / 256, 256>>>(out);
}

// round 15
// speedup vs baseline: 2.0412x; 1.3500x over previous
#include <cuda_runtime.h>
#include <cuda_bf16.h>
#include <cuda_fp16.h>
#include <cstdint>

// Problem constants
#define Bq   4
#define Nq   2048
#define FIN  128
#define Hq   4
#define Dq   64
#define ALPHA 0.2f

// Scratch
__device__ float g_h[Bq * Hq * Nq * Dq];    // [bh][n][d] (8 MB)
__device__ float g_o[Bq * Hq * Nq * Dq];
__device__ float g_ei[Bq * Hq * Nq];
__device__ float g_ej[Bq * Hq * Nq];
// U/L tiles (fp16): 2 arrays [bh][2048][72] (cols 0-63 data, 64 den, 65-71 zero)
#define ULSTRIDE 2359296ull   // 16*2048*72
__device__ uint16_t g_ul[2 * ULSTRIDE];

// ---- packed f32x2 helpers (k_gemm) ----------------------------------------
__device__ __forceinline__ unsigned long long pk2(float lo, float hi) {
    unsigned long long r;
    asm("mov.b64 %0, {%1,%2};" : "=l"(r) : "f"(lo), "f"(hi));
    return r;
}
__device__ __forceinline__ void fma2(unsigned long long& d,
                                     unsigned long long a,
                                     unsigned long long b) {
    asm("fma.rn.f32x2 %0, %1, %2, %0;" : "+l"(d) : "l"(a), "l"(b));
}
__device__ __forceinline__ float2 upk(unsigned long long v) {
    float2 f;
    asm("mov.b64 {%0,%1}, %2;" : "=f"(f.x), "=f"(f.y) : "l"(v));
    return f;
}

// ---- mma.sync helpers -----------------------------------------------------
__device__ __forceinline__ uint32_t s2u(const void* p) {
    uint32_t a;
    asm("{ .reg .u64 t; cvta.to.shared.u64 t, %1; cvt.u32.u64 %0, t; }"
        : "=r"(a) : "l"(p));
    return a;
}
__device__ __forceinline__ void ldsm4(uint32_t* r, uint32_t a) {
    asm volatile("ldmatrix.sync.aligned.m8n8.x4.shared.b16 {%0,%1,%2,%3},[%4];"
                 : "=r"(r[0]), "=r"(r[1]), "=r"(r[2]), "=r"(r[3]) : "r"(a));
}
__device__ __forceinline__ void ldsm4t(uint32_t* r, uint32_t a) {
    asm volatile(
        "ldmatrix.sync.aligned.m8n8.x4.trans.shared.b16 {%0,%1,%2,%3},[%4];"
        : "=r"(r[0]), "=r"(r[1]), "=r"(r[2]), "=r"(r[3]) : "r"(a));
}
__device__ __forceinline__ void ldsm2t(uint32_t* r, uint32_t a) {
    asm volatile(
        "ldmatrix.sync.aligned.m8n8.x2.trans.shared.b16 {%0,%1},[%2];"
        : "=r"(r[0]), "=r"(r[1]) : "r"(a));
}
// fp16 MMA: m16n8k16, f32 accumulate
__device__ __forceinline__ void mmah(float* c, const uint32_t* a,
                                     const uint32_t* b) {
    asm volatile(
        "mma.sync.aligned.m16n8k16.row.col.f32.f16.f16.f32 "
        "{%0,%1,%2,%3},{%4,%5,%6,%7},{%8,%9},{%0,%1,%2,%3};"
        : "+f"(c[0]), "+f"(c[1]), "+f"(c[2]), "+f"(c[3])
        : "r"(a[0]), "r"(a[1]), "r"(a[2]), "r"(a[3]), "r"(b[0]), "r"(b[1]));
}
__device__ __forceinline__ uint32_t phf(float x, float y) {
    __half2 t = __floats2half2_rn(x, y);
    return *(uint32_t*)&t;
}

// ---------------------------------------------------------------------------
// Kernel 1: h = x @ W -> g_h[b][head][n][d]
// ---------------------------------------------------------------------------
__global__ __launch_bounds__(256) void k_gemm(const float* __restrict__ x,
                                              const float* __restrict__ W) {
    __shared__ float Ws[32 * 256];
    __shared__ float xs[32 * 33];

    const int tid  = threadIdx.x;
    const int row0 = blockIdx.x * 32;
    const int ty   = tid >> 4;
    const int tx   = tid & 15;

    unsigned long long acc2[2][8];
#pragma unroll
    for (int r = 0; r < 2; r++)
#pragma unroll
        for (int c = 0; c < 8; c++) acc2[r][c] = 0ull;

    for (int kc = 0; kc < FIN; kc += 32) {
        __syncthreads();
        const float4* W4 = (const float4*)(W + kc * 256);
#pragma unroll
        for (int t = 0; t < 8; t++) {
            int idx = tid + 256 * t;
            ((float4*)Ws)[idx] = W4[idx];
        }
        {
            int r  = tid >> 3;
            int kq = tid & 7;
            float4 v = *(const float4*)(x + (size_t)(row0 + r) * FIN + kc + kq * 4);
            float* dst = &xs[r * 33 + kq * 4];
            dst[0] = v.x; dst[1] = v.y; dst[2] = v.z; dst[3] = v.w;
        }
        __syncthreads();
#pragma unroll
        for (int k = 0; k < 32; k++) {
            float x0 = xs[(ty * 2 + 0) * 33 + k];
            float x1 = xs[(ty * 2 + 1) * 33 + k];
            unsigned long long xp0 = pk2(x0, x0);
            unsigned long long xp1 = pk2(x1, x1);
#pragma unroll
            for (int c = 0; c < 8; c++) {
                unsigned long long wv =
                    *(const unsigned long long*)&Ws[k * 256 + tx * 2 + c * 32];
                fma2(acc2[0][c], xp0, wv);
                fma2(acc2[1][c], xp1, wv);
            }
        }
    }
#pragma unroll
    for (int r = 0; r < 2; r++) {
        int g = row0 + ty * 2 + r;
        int b = g / Nq;
        int n = g % Nq;
#pragma unroll
        for (int c = 0; c < 8; c++) {
            int o    = tx * 2 + c * 32;
            int head = o >> 6;
            int d    = o & 63;
            float2 v = upk(acc2[r][c]);
            *(float2*)&g_h[(((size_t)b * Hq + head) * Nq + n) * Dq + d] = v;
        }
    }
}

// ---------------------------------------------------------------------------
// Kernel 2: ei/ej per (b,head,n). One warp per row.
// ---------------------------------------------------------------------------
__global__ __launch_bounds__(256) void k_ev(const float* __restrict__ a) {
    int task = blockIdx.x * 8 + (threadIdx.x >> 5);
    int lane = threadIdx.x & 31;
    const float* hr = g_h + (size_t)task * Dq;
    float v0 = hr[lane], v1 = hr[lane + 32];
    float e1 = v0 * a[lane]      + v1 * a[lane + 32];
    float e2 = v0 * a[64 + lane] + v1 * a[96 + lane];
#pragma unroll
    for (int off = 16; off > 0; off >>= 1) {
        e1 += __shfl_down_sync(0xffffffffu, e1, off);
        e2 += __shfl_down_sync(0xffffffffu, e2, off);
    }
    if (lane == 0) {
        g_ei[task] = e1;
        g_ej[task] = e2;
    }
}

// ---------------------------------------------------------------------------
// Kernel 3: k_prep — build U/L (fp16 + den col) once per (bh, j).
// ---------------------------------------------------------------------------
__global__ __launch_bounds__(256) void k_prep() {
    int gidx = blockIdx.x * 256 + threadIdx.x;   // 16*2048*4
    int dq   = (gidx & 3) * 16;
    int j    = (gidx >> 2) & (Nq - 1);
    int bh   = gidx >> 13;

    float e  = g_ej[bh * Nq + j];
    float x1 = __expf(e);
    float x2 = __expf(0.2f * e);

    const float* vr = g_h + ((size_t)bh * Nq + j) * Dq + dq;
    float v[16];
#pragma unroll
    for (int g = 0; g < 4; g++) {
        float4 f = *(const float4*)(vr + 4 * g);
        v[4 * g] = f.x; v[4 * g + 1] = f.y;
        v[4 * g + 2] = f.z; v[4 * g + 3] = f.w;
    }
    uint32_t uh[8], lh[8];
#pragma unroll
    for (int g = 0; g < 8; g++) {
        uh[g] = phf(v[2 * g] * x1, v[2 * g + 1] * x1);
        lh[g] = phf(v[2 * g] * x2, v[2 * g + 1] * x2);
    }
    size_t row = ((size_t)bh * Nq + j) * 72;
    uint16_t* Uh = g_ul;
    uint16_t* Lh = g_ul + ULSTRIDE;
    *(uint4*)(Uh + row + dq)     = *(uint4*)&uh[0];
    *(uint4*)(Uh + row + dq + 8) = *(uint4*)&uh[4];
    *(uint4*)(Lh + row + dq)     = *(uint4*)&lh[0];
    *(uint4*)(Lh + row + dq + 8) = *(uint4*)&lh[4];
    if ((gidx & 3) == 3) {       // den column 64 (+ zeros 65-71)
        *(uint4*)(Uh + row + 64) = make_uint4(phf(x1, 0.f), 0, 0, 0);
        *(uint4*)(Lh + row + 64) = make_uint4(phf(x2, 0.f), 0, 0, 0);
    }
}

// ---------------------------------------------------------------------------
// Kernel 4: GAT attention via mma.sync fp16, v5 (single GEMM per path).
// ---------------------------------------------------------------------------
#define PITA 144    // A/B mask tile row pitch bytes
#define PITU 144    // U/L tile row pitch bytes (72 fp16)
#define OFF_B   18432
#define OFF_UH  36864
#define OFF_LH  46080
#define OFF_EJ  55296
#define SMEM_AT 63488

__global__ __launch_bounds__(256, 2) void k_attn(const int* __restrict__ adj) {
    extern __shared__ char dyn[];
    __shared__ float ei_s[128];
    __shared__ float dns1[128], dns2[128];

    char*  Asm = dyn;
    char*  Bsm = dyn + OFF_B;
    char*  Uhm = dyn + OFF_UH;
    float* ejf = (float*)(dyn + OFF_EJ);

    const int tid  = threadIdx.x;
    const int wid  = tid >> 5;
    const int lane = tid & 31;
    const int it   = blockIdx.x & 15;
    const int head = (blockIdx.x >> 4) & 3;
    const int b    = blockIdx.x >> 6;
    const int i0   = it * 128;
    const int bh   = b * Hq + head;
    const int mg   = wid >> 1;
    const int ngrp = wid & 1;
    const int m0   = mg * 32;
    const int n0   = ngrp * 32;

#pragma unroll
    for (int t = 0; t < 8; t++) {
        int j = tid + 256 * t;
        ejf[j] = g_ej[bh * Nq + j];
    }
    if (tid < 128) ei_s[tid] = g_ei[bh * Nq + i0 + tid];
    __syncthreads();

    const uint32_t AsU = s2u(Asm), BsU = s2u(Bsm);
    const uint32_t UhU = s2u(Uhm);
    const uint32_t LhU = UhU + 9216;
    const uint32_t aL = AsU + (uint32_t)(m0 + (lane & 15)) * PITA +
                        (uint32_t)(lane >> 4) * 16;
    const uint32_t bL = BsU + (uint32_t)(m0 + (lane & 15)) * PITA +
                        (uint32_t)(lane >> 4) * 16;
    const uint32_t uB = (uint32_t)(lane & 15) * PITU +
                        (uint32_t)(lane >> 4) * 16 + (uint32_t)n0 * 2;
    const uint32_t uD = (uint32_t)(lane & 15) * PITU + 128;  // den col 64

    const int   mi   = tid >> 1;
    const int   jh   = (tid & 1) * 32;
    const float eIv  = ei_s[mi];
    const int*  ar0  = adj + ((size_t)b * Nq + i0 + mi) * Nq;
    // cp.async mapping: threads 0-127 copy one row each (2 tiles x 64 rows)
    const int   cpa  = (tid >> 6) & 1;        // tile 0..1
    const int   cpr  = tid & 63;              // row 0..63
    const uint16_t* cpsrc0 = g_ul + (size_t)cpa * ULSTRIDE +
                             ((size_t)bh * Nq + cpr) * 72;
    const uint32_t  cpdst  = UhU + (uint32_t)cpa * 9216 + (uint32_t)cpr * PITU;

    float C1[2][4][4], C2[2][4][4];
    float C1d[2][4], C2d[2][4];
#pragma unroll
    for (int mt = 0; mt < 2; mt++) {
#pragma unroll
        for (int nt = 0; nt < 4; nt++)
#pragma unroll
            for (int q = 0; q < 4; q++) {
                C1[mt][nt][q] = 0.f;
                C2[mt][nt][q] = 0.f;
            }
#pragma unroll
        for (int q = 0; q < 4; q++) { C1d[mt][q] = 0.f; C2d[mt][q] = 0.f; }
    }

    for (int ch = 0; ch < 32; ch++) {
        const int j0 = ch * 64;
        __syncthreads();   // previous chunk's smem reads done

        // ---- prefetch U/L tiles (async, overlaps mask build) ----
        if (tid < 128) {
            const uint16_t* src = cpsrc0 + (size_t)j0 * 72;
#pragma unroll
            for (int seg = 0; seg < 9; seg++) {
                asm volatile("cp.async.ca.shared.global [%0], [%1], 16;"
                             :: "r"(cpdst + seg * 16), "l"(src + seg * 8)
                             : "memory");
            }
        }
        asm volatile("cp.async.commit_group;" ::: "memory");

        // ---- masks A,B: thread owns row mi, 32 j (branch-free, fp16 1.0) ----
        {
            const int4* ap = (const int4*)(ar0 + j0 + jh);
#pragma unroll
            for (int q = 0; q < 8; q++) {
                int4 m = ap[q];
                int j  = jh + 4 * q;
                float s0 = eIv + ejf[j0 + j + 0];
                float s1 = eIv + ejf[j0 + j + 1];
                float s2 = eIv + ejf[j0 + j + 2];
                float s3 = eIv + ejf[j0 + j + 3];
                uint32_t a0 = (m.x && s0 >= 0.f) ? 0x3C00u : 0u;
                uint32_t a1 = (m.y && s1 >= 0.f) ? 0x3C00u : 0u;
                uint32_t a2 = (m.z && s2 >= 0.f) ? 0x3C00u : 0u;
                uint32_t a3 = (m.w && s3 >= 0.f) ? 0x3C00u : 0u;
                uint32_t b0 = (m.x && s0 < 0.f) ? 0x3C00u : 0u;
                uint32_t b1 = (m.y && s1 < 0.f) ? 0x3C00u : 0u;
                uint32_t b2 = (m.z && s2 < 0.f) ? 0x3C00u : 0u;
                uint32_t b3 = (m.w && s3 < 0.f) ? 0x3C00u : 0u;
                uint2 pa = make_uint2(a0 | (a1 << 16), a2 | (a3 << 16));
                uint2 pb = make_uint2(b0 | (b1 << 16), b2 | (b3 << 16));
                *(uint2*)(Asm + mi * PITA + j * 2) = pa;
                *(uint2*)(Bsm + mi * PITA + j * 2) = pb;
            }
        }

        asm volatile("cp.async.wait_group 0;" ::: "memory");
        __syncthreads();

        // ---- compute: 4 k16 steps, warp tile 32x32 (+den on ngrp1) ----
#pragma unroll
        for (int ks = 0; ks < 4; ks++) {
            uint32_t amA[2][4], amB[2][4];
            ldsm4(amA[0], aL + ks * 32);
            ldsm4(amA[1], aL + 16 * PITA + ks * 32);
            ldsm4(amB[0], bL + ks * 32);
            ldsm4(amB[1], bL + 16 * PITA + ks * 32);
            const uint32_t ub = uB + (uint32_t)(ks * 16 * PITU);
#pragma unroll
            for (int ng = 0; ng < 2; ng++) {
                uint32_t f[4];
                ldsm4t(f, UhU + ub + ng * 32);
                mmah(C1[0][2 * ng],     amA[0], f);
                mmah(C1[0][2 * ng + 1], amA[0], f + 2);
                mmah(C1[1][2 * ng],     amA[1], f);
                mmah(C1[1][2 * ng + 1], amA[1], f + 2);
                ldsm4t(f, LhU + ub + ng * 32);
                mmah(C2[0][2 * ng],     amB[0], f);
                mmah(C2[0][2 * ng + 1], amB[0], f + 2);
                mmah(C2[1][2 * ng],     amB[1], f);
                mmah(C2[1][2 * ng + 1], amB[1], f + 2);
            }
            if (ngrp) {   // den tile (col 64), warp-uniform branch
                const uint32_t ud = uD + (uint32_t)(ks * 16 * PITU);
                uint32_t t0[2];
                ldsm2t(t0, UhU + ud);
                mmah(C1d[0], amA[0], t0); mmah(C1d[1], amA[1], t0);
                ldsm2t(t0, LhU + ud);
                mmah(C2d[0], amB[0], t0); mmah(C2d[1], amB[1], t0);
            }
        }
    }

    // ---- stage den through smem ----
    if (ngrp && (lane & 3) == 0) {
        int r0 = lane >> 2;
#pragma unroll
        for (int mt = 0; mt < 2; mt++) {
            dns1[m0 + mt * 16 + r0]     = C1d[mt][0];
            dns2[m0 + mt * 16 + r0]     = C2d[mt][0];
            dns1[m0 + mt * 16 + r0 + 8] = C1d[mt][2];
            dns2[m0 + mt * 16 + r0 + 8] = C2d[mt][2];
        }
    }
    __syncthreads();

    // ---- readout ----
    const int r0 = lane >> 2;
    const int c0 = (lane & 3) * 2;
#pragma unroll
    for (int mt = 0; mt < 2; mt++) {
#pragma unroll
        for (int half = 0; half < 2; half++) {
            int row = m0 + mt * 16 + r0 + half * 8;
            float sA = __expf(ei_s[row]);
            float sB = __expf(0.2f * ei_s[row]);
            float den = sA * dns1[row] + sB * dns2[row];
            float inv = 1.f / den;
            float* og = g_o + ((size_t)bh * Nq + i0 + row) * Dq;
#pragma unroll
            for (int nt = 0; nt < 4; nt++) {
                float2 o;
                o.x = (sA * C1[mt][nt][2 * half] + sB * C2[mt][nt][2 * half]) * inv;
                o.y = (sA * C1[mt][nt][2 * half + 1] +
                       sB * C2[mt][nt][2 * half + 1]) * inv;
                *(float2*)&og[n0 + nt * 8 + c0] = o;
            }
        }
    }
}

// ---------------------------------------------------------------------------
// Kernel 5: out[b][n][d] = mean over heads of g_o
// ---------------------------------------------------------------------------
__global__ __launch_bounds__(256) void k_mean(float* __restrict__ out) {
    int idx = blockIdx.x * 256 + threadIdx.x;
    if (idx >= Bq * Nq * Dq) return;
    int d = idx & 63;
    int n = (idx >> 6) & (Nq - 1);
    int b = idx >> 17;
    float s = 0.f;
#pragma unroll
    for (int h = 0; h < Hq; h++)
        s += g_o[(((size_t)b * Hq + h) * Nq + n) * Dq + d];
    out[idx] = 0.25f * s;
}

// ---------------------------------------------------------------------------
extern "C" void kernel_launch(void* const* d_in, const int* in_sizes, int n_in,
                              void* d_out, int out_size) {
    const float* x   = (const float*)d_in[0];
    const int*   adj = (const int*)  d_in[1];
    const float* W   = (const float*)d_in[2];
    const float* a   = (const float*)d_in[3];
    float*       out = (float*)d_out;

    cudaFuncSetAttribute(k_attn, cudaFuncAttributeMaxDynamicSharedMemorySize,
                         SMEM_AT);

    k_gemm<<<(Bq * Nq) / 32, 256>>>(x, W);
    k_ev  <<<(Bq * Hq * Nq) / 8, 256>>>(a);
    k_prep<<<(16 * Nq * 4) / 256, 256>>>();
    k_attn<<<Bq * Hq * (Nq / 128), 256, SMEM_AT>>>(adj);
    k_mean<<<(Bq * Nq * Dq + 255) / 256, 256>>>(out);
}

// round 16
// speedup vs baseline: 2.2168x; 1.0860x over previous
#include <cuda_runtime.h>
#include <cuda_bf16.h>
#include <cuda_fp16.h>
#include <cstdint>

// Problem constants
#define Bq   4
#define Nq   2048
#define FIN  128
#define Hq   4
#define Dq   64
#define ALPHA 0.2f

// Scratch
__device__ float g_h[Bq * Hq * Nq * Dq];    // [bh][n][d] (8 MB)
__device__ float g_o[Bq * Hq * Nq * Dq];
__device__ float g_ei[Bq * Hq * Nq];
__device__ float g_ej[Bq * Hq * Nq];
// U/L tiles (fp16): 2 arrays [bh][2048][72] (cols 0-63 data, 64 den, 65-71 zero)
#define ULSTRIDE 2359296ull   // 16*2048*72
__device__ uint16_t g_ul[2 * ULSTRIDE];
// bit-packed adjacency: [b][n][64 words], word w bit k = adj[b][n][w*32+k]
__device__ uint32_t g_adjp[Bq * Nq * 64];

// ---- packed f32x2 helpers (k_gemm) ----------------------------------------
__device__ __forceinline__ unsigned long long pk2(float lo, float hi) {
    unsigned long long r;
    asm("mov.b64 %0, {%1,%2};" : "=l"(r) : "f"(lo), "f"(hi));
    return r;
}
__device__ __forceinline__ void fma2(unsigned long long& d,
                                     unsigned long long a,
                                     unsigned long long b) {
    asm("fma.rn.f32x2 %0, %1, %2, %0;" : "+l"(d) : "l"(a), "l"(b));
}
__device__ __forceinline__ float2 upk(unsigned long long v) {
    float2 f;
    asm("mov.b64 {%0,%1}, %2;" : "=f"(f.x), "=f"(f.y) : "l"(v));
    return f;
}

// ---- mma.sync helpers -----------------------------------------------------
__device__ __forceinline__ uint32_t s2u(const void* p) {
    uint32_t a;
    asm("{ .reg .u64 t; cvta.to.shared.u64 t, %1; cvt.u32.u64 %0, t; }"
        : "=r"(a) : "l"(p));
    return a;
}
__device__ __forceinline__ void ldsm4t(uint32_t* r, uint32_t a) {
    asm volatile(
        "ldmatrix.sync.aligned.m8n8.x4.trans.shared.b16 {%0,%1,%2,%3},[%4];"
        : "=r"(r[0]), "=r"(r[1]), "=r"(r[2]), "=r"(r[3]) : "r"(a));
}
__device__ __forceinline__ void ldsm2t(uint32_t* r, uint32_t a) {
    asm volatile(
        "ldmatrix.sync.aligned.m8n8.x2.trans.shared.b16 {%0,%1},[%2];"
        : "=r"(r[0]), "=r"(r[1]) : "r"(a));
}
__device__ __forceinline__ void mmah(float* c, const uint32_t* a,
                                     const uint32_t* b) {
    asm volatile(
        "mma.sync.aligned.m16n8k16.row.col.f32.f16.f16.f32 "
        "{%0,%1,%2,%3},{%4,%5,%6,%7},{%8,%9},{%0,%1,%2,%3};"
        : "+f"(c[0]), "+f"(c[1]), "+f"(c[2]), "+f"(c[3])
        : "r"(a[0]), "r"(a[1]), "r"(a[2]), "r"(a[3]), "r"(b[0]), "r"(b[1]));
}
__device__ __forceinline__ uint32_t phf(float x, float y) {
    __half2 t = __floats2half2_rn(x, y);
    return *(uint32_t*)&t;
}
// 2 mask bits -> packed fp16 {0,1} pair
__device__ __forceinline__ uint32_t b2h(uint32_t x) {
    return (x & 1u) * 0x3C00u + (x & 2u) * 0x1E000000u;
}

// ---------------------------------------------------------------------------
// Kernel 1: h = x @ W -> g_h[b][head][n][d]
// ---------------------------------------------------------------------------
__global__ __launch_bounds__(256) void k_gemm(const float* __restrict__ x,
                                              const float* __restrict__ W) {
    __shared__ float Ws[32 * 256];
    __shared__ float xs[32 * 33];

    const int tid  = threadIdx.x;
    const int row0 = blockIdx.x * 32;
    const int ty   = tid >> 4;
    const int tx   = tid & 15;

    unsigned long long acc2[2][8];
#pragma unroll
    for (int r = 0; r < 2; r++)
#pragma unroll
        for (int c = 0; c < 8; c++) acc2[r][c] = 0ull;

    for (int kc = 0; kc < FIN; kc += 32) {
        __syncthreads();
        const float4* W4 = (const float4*)(W + kc * 256);
#pragma unroll
        for (int t = 0; t < 8; t++) {
            int idx = tid + 256 * t;
            ((float4*)Ws)[idx] = W4[idx];
        }
        {
            int r  = tid >> 3;
            int kq = tid & 7;
            float4 v = *(const float4*)(x + (size_t)(row0 + r) * FIN + kc + kq * 4);
            float* dst = &xs[r * 33 + kq * 4];
            dst[0] = v.x; dst[1] = v.y; dst[2] = v.z; dst[3] = v.w;
        }
        __syncthreads();
#pragma unroll
        for (int k = 0; k < 32; k++) {
            float x0 = xs[(ty * 2 + 0) * 33 + k];
            float x1 = xs[(ty * 2 + 1) * 33 + k];
            unsigned long long xp0 = pk2(x0, x0);
            unsigned long long xp1 = pk2(x1, x1);
#pragma unroll
            for (int c = 0; c < 8; c++) {
                unsigned long long wv =
                    *(const unsigned long long*)&Ws[k * 256 + tx * 2 + c * 32];
                fma2(acc2[0][c], xp0, wv);
                fma2(acc2[1][c], xp1, wv);
            }
        }
    }
#pragma unroll
    for (int r = 0; r < 2; r++) {
        int g = row0 + ty * 2 + r;
        int b = g / Nq;
        int n = g % Nq;
#pragma unroll
        for (int c = 0; c < 8; c++) {
            int o    = tx * 2 + c * 32;
            int head = o >> 6;
            int d    = o & 63;
            float2 v = upk(acc2[r][c]);
            *(float2*)&g_h[(((size_t)b * Hq + head) * Nq + n) * Dq + d] = v;
        }
    }
}

// ---------------------------------------------------------------------------
// Kernel 2: ei/ej per (b,head,n). One warp per row.
// ---------------------------------------------------------------------------
__global__ __launch_bounds__(256) void k_ev(const float* __restrict__ a) {
    int task = blockIdx.x * 8 + (threadIdx.x >> 5);
    int lane = threadIdx.x & 31;
    const float* hr = g_h + (size_t)task * Dq;
    float v0 = hr[lane], v1 = hr[lane + 32];
    float e1 = v0 * a[lane]      + v1 * a[lane + 32];
    float e2 = v0 * a[64 + lane] + v1 * a[96 + lane];
#pragma unroll
    for (int off = 16; off > 0; off >>= 1) {
        e1 += __shfl_down_sync(0xffffffffu, e1, off);
        e2 += __shfl_down_sync(0xffffffffu, e2, off);
    }
    if (lane == 0) {
        g_ei[task] = e1;
        g_ej[task] = e2;
    }
}

// ---------------------------------------------------------------------------
// Kernel 3: k_prep — blocks 0-511: build U/L fp16 (+den col) per (bh, j);
//           blocks 512-2559: bit-pack adj into g_adjp.
// ---------------------------------------------------------------------------
__global__ __launch_bounds__(256) void k_prep(const int* __restrict__ adj) {
    if (blockIdx.x >= 512) {
        int gi = (blockIdx.x - 512) * 256 + threadIdx.x;   // < 4*2048*64
        const int4* src = (const int4*)adj + (size_t)gi * 8;
        uint32_t w = 0;
#pragma unroll
        for (int q = 0; q < 8; q++) {
            int4 m = src[q];
            w |= (m.x ? 1u : 0u) << (q * 4);
            w |= (m.y ? 1u : 0u) << (q * 4 + 1);
            w |= (m.z ? 1u : 0u) << (q * 4 + 2);
            w |= (m.w ? 1u : 0u) << (q * 4 + 3);
        }
        g_adjp[gi] = w;
        return;
    }

    int gidx = blockIdx.x * 256 + threadIdx.x;   // 16*2048*4
    int dq   = (gidx & 3) * 16;
    int j    = (gidx >> 2) & (Nq - 1);
    int bh   = gidx >> 13;

    float e  = g_ej[bh * Nq + j];
    float x1 = __expf(e);
    float x2 = __expf(0.2f * e);

    const float* vr = g_h + ((size_t)bh * Nq + j) * Dq + dq;
    float v[16];
#pragma unroll
    for (int g = 0; g < 4; g++) {
        float4 f = *(const float4*)(vr + 4 * g);
        v[4 * g] = f.x; v[4 * g + 1] = f.y;
        v[4 * g + 2] = f.z; v[4 * g + 3] = f.w;
    }
    uint32_t uh[8], lh[8];
#pragma unroll
    for (int g = 0; g < 8; g++) {
        uh[g] = phf(v[2 * g] * x1, v[2 * g + 1] * x1);
        lh[g] = phf(v[2 * g] * x2, v[2 * g + 1] * x2);
    }
    size_t row = ((size_t)bh * Nq + j) * 72;
    uint16_t* Uh = g_ul;
    uint16_t* Lh = g_ul + ULSTRIDE;
    *(uint4*)(Uh + row + dq)     = *(uint4*)&uh[0];
    *(uint4*)(Uh + row + dq + 8) = *(uint4*)&uh[4];
    *(uint4*)(Lh + row + dq)     = *(uint4*)&lh[0];
    *(uint4*)(Lh + row + dq + 8) = *(uint4*)&lh[4];
    if ((gidx & 3) == 3) {       // den column 64 (+ zeros 65-71)
        *(uint4*)(Uh + row + 64) = make_uint4(phf(x1, 0.f), 0, 0, 0);
        *(uint4*)(Lh + row + 64) = make_uint4(phf(x2, 0.f), 0, 0, 0);
    }
}

// ---------------------------------------------------------------------------
// Kernel 4: GAT attention, v6: masks built IN REGISTERS from bit-packed adj
// and precomputed sign bits; U/L fp16 double-buffered via cp.async.
// ---------------------------------------------------------------------------
#define PITU 144          // U/L tile row pitch bytes (72 fp16)
#define ST_STRIDE 18432   // one stage: Uh(9216) + Lh(9216)
#define SGNW 65           // sign row stride in words (conflict-free)
#define OFF_SGN 36864     // uint32[128*65] = 33280 B
#define OFF_EJ  70144     // float[2048] = 8192 B
#define SMEM_AT 78336

__global__ __launch_bounds__(256, 2) void k_attn() {
    extern __shared__ char dyn[];
    __shared__ float ei_s[128];
    __shared__ float dns1[128], dns2[128];

    uint32_t* sgn = (uint32_t*)(dyn + OFF_SGN);
    float*    ejf = (float*)(dyn + OFF_EJ);

    const int tid  = threadIdx.x;
    const int wid  = tid >> 5;
    const int lane = tid & 31;
    const int it   = blockIdx.x & 15;
    const int head = (blockIdx.x >> 4) & 3;
    const int b    = blockIdx.x >> 6;
    const int i0   = it * 128;
    const int bh   = b * Hq + head;
    const int mg   = wid >> 1;
    const int ngrp = wid & 1;
    const int m0   = mg * 32;
    const int n0   = ngrp * 32;
    const int g    = lane >> 2;
    const int t2   = (lane & 3) * 2;

#pragma unroll
    for (int t = 0; t < 8; t++) {
        int j = tid + 256 * t;
        ejf[j] = g_ej[bh * Nq + j];
    }
    if (tid < 128) ei_s[tid] = g_ei[bh * Nq + i0 + tid];

    const uint32_t UhU = s2u(dyn);
    // cp.async mapping: threads 0-127 copy one row each (2 tiles x 64 rows)
    const int cpa = (tid >> 6) & 1;
    const int cpr = tid & 63;
    const uint16_t* cpsrc0 = g_ul + (size_t)cpa * ULSTRIDE +
                             ((size_t)bh * Nq + cpr) * 72;
    const uint32_t cpdstB = UhU + (uint32_t)cpa * 9216 + (uint32_t)cpr * PITU;

    // prologue: chunk 0 into stage 0
    if (tid < 128) {
#pragma unroll
        for (int seg = 0; seg < 9; seg++)
            asm volatile("cp.async.ca.shared.global [%0], [%1], 16;"
                         :: "r"(cpdstB + seg * 16), "l"(cpsrc0 + seg * 8)
                         : "memory");
    }
    asm volatile("cp.async.commit_group;" ::: "memory");

    __syncthreads();   // ejf / ei_s ready

    // sign bits for all (i, j): sgn[i][w] bit k = (ej[w*32+k] >= -ei[i])
    {
        int row   = tid >> 1;
        float thr = -ei_s[row];
        int w0    = (tid & 1) * 32;
        for (int w = 0; w < 32; w++) {
            uint32_t sg = 0;
#pragma unroll
            for (int k = 0; k < 32; k++)
                sg |= (ejf[(w0 + w) * 32 + k] >= thr) ? (1u << k) : 0u;
            sgn[row * SGNW + w0 + w] = sg;
        }
    }

    const uint32_t* adjp_b = g_adjp + ((size_t)b * Nq + i0) * 64;

    float C1[2][4][4], C2[2][4][4];
    float C1d[2][4], C2d[2][4];
#pragma unroll
    for (int mt = 0; mt < 2; mt++) {
#pragma unroll
        for (int nt = 0; nt < 4; nt++)
#pragma unroll
            for (int q = 0; q < 4; q++) {
                C1[mt][nt][q] = 0.f;
                C2[mt][nt][q] = 0.f;
            }
#pragma unroll
        for (int q = 0; q < 4; q++) { C1d[mt][q] = 0.f; C2d[mt][q] = 0.f; }
    }

    const uint32_t uB = (uint32_t)(lane & 15) * PITU +
                        (uint32_t)(lane >> 4) * 16 + (uint32_t)n0 * 2;
    const uint32_t uD = (uint32_t)(lane & 15) * PITU + 128;

    for (int ch = 0; ch < 32; ch++) {
        // issue next chunk's U/L into the other stage (freed by compute ch-1)
        if (ch < 31) {
            if (tid < 128) {
                const uint16_t* src = cpsrc0 + (size_t)(ch + 1) * 64 * 72;
                uint32_t dst = cpdstB + (((ch + 1) & 1) ? ST_STRIDE : 0);
#pragma unroll
                for (int seg = 0; seg < 9; seg++)
                    asm volatile("cp.async.ca.shared.global [%0], [%1], 16;"
                                 :: "r"(dst + seg * 16), "l"(src + seg * 8)
                                 : "memory");
            }
            asm volatile("cp.async.commit_group;" ::: "memory");
        }

        // mask words for this chunk (registers): A = adj&sgn, B = adj&~sgn
        uint32_t wA[2][2][2], wB[2][2][2];   // [mt][rr][word]
#pragma unroll
        for (int mt = 0; mt < 2; mt++)
#pragma unroll
            for (int rr = 0; rr < 2; rr++) {
                int r = m0 + mt * 16 + g + rr * 8;
                uint32_t a0 = adjp_b[(size_t)r * 64 + ch * 2];
                uint32_t a1 = adjp_b[(size_t)r * 64 + ch * 2 + 1];
                uint32_t s0 = sgn[r * SGNW + ch * 2];
                uint32_t s1 = sgn[r * SGNW + ch * 2 + 1];
                wA[mt][rr][0] = a0 & s0;
                wA[mt][rr][1] = a1 & s1;
                wB[mt][rr][0] = a0 & ~s0;
                wB[mt][rr][1] = a1 & ~s1;
            }

        if (ch < 31) asm volatile("cp.async.wait_group 1;" ::: "memory");
        else         asm volatile("cp.async.wait_group 0;" ::: "memory");
        __syncthreads();

        const uint32_t base = UhU + ((ch & 1) ? ST_STRIDE : 0);
#pragma unroll
        for (int ks = 0; ks < 4; ks++) {
            const int wsel = ks >> 1;
            const int sh   = (ks & 1) * 16 + t2;
            uint32_t amA[2][4], amB[2][4];
#pragma unroll
            for (int mt = 0; mt < 2; mt++) {
                uint32_t x;
                x = wA[mt][0][wsel] >> sh;       amA[mt][0] = b2h(x);
                x = wA[mt][1][wsel] >> sh;       amA[mt][1] = b2h(x);
                x = wA[mt][0][wsel] >> (sh + 8); amA[mt][2] = b2h(x);
                x = wA[mt][1][wsel] >> (sh + 8); amA[mt][3] = b2h(x);
                x = wB[mt][0][wsel] >> sh;       amB[mt][0] = b2h(x);
                x = wB[mt][1][wsel] >> sh;       amB[mt][1] = b2h(x);
                x = wB[mt][0][wsel] >> (sh + 8); amB[mt][2] = b2h(x);
                x = wB[mt][1][wsel] >> (sh + 8); amB[mt][3] = b2h(x);
            }
            const uint32_t ub = base + uB + (uint32_t)(ks * 16 * PITU);
#pragma unroll
            for (int ng = 0; ng < 2; ng++) {
                uint32_t f[4];
                ldsm4t(f, ub + ng * 32);            // Uh
                mmah(C1[0][2 * ng],     amA[0], f);
                mmah(C1[0][2 * ng + 1], amA[0], f + 2);
                mmah(C1[1][2 * ng],     amA[1], f);
                mmah(C1[1][2 * ng + 1], amA[1], f + 2);
                ldsm4t(f, ub + 9216 + ng * 32);     // Lh
                mmah(C2[0][2 * ng],     amB[0], f);
                mmah(C2[0][2 * ng + 1], amB[0], f + 2);
                mmah(C2[1][2 * ng],     amB[1], f);
                mmah(C2[1][2 * ng + 1], amB[1], f + 2);
            }
            if (ngrp) {   // den tile (col 64), warp-uniform branch
                const uint32_t ud = base + uD + (uint32_t)(ks * 16 * PITU);
                uint32_t t0[2];
                ldsm2t(t0, ud);
                mmah(C1d[0], amA[0], t0); mmah(C1d[1], amA[1], t0);
                ldsm2t(t0, ud + 9216);
                mmah(C2d[0], amB[0], t0); mmah(C2d[1], amB[1], t0);
            }
        }
        __syncthreads();   // stage reuse guard before next issue
    }

    // ---- stage den through smem ----
    if (ngrp && (lane & 3) == 0) {
        int r0 = lane >> 2;
#pragma unroll
        for (int mt = 0; mt < 2; mt++) {
            dns1[m0 + mt * 16 + r0]     = C1d[mt][0];
            dns2[m0 + mt * 16 + r0]     = C2d[mt][0];
            dns1[m0 + mt * 16 + r0 + 8] = C1d[mt][2];
            dns2[m0 + mt * 16 + r0 + 8] = C2d[mt][2];
        }
    }
    __syncthreads();

    // ---- readout ----
    const int r0 = lane >> 2;
    const int c0 = (lane & 3) * 2;
#pragma unroll
    for (int mt = 0; mt < 2; mt++) {
#pragma unroll
        for (int half = 0; half < 2; half++) {
            int row = m0 + mt * 16 + r0 + half * 8;
            float sA = __expf(ei_s[row]);
            float sB = __expf(0.2f * ei_s[row]);
            float den = sA * dns1[row] + sB * dns2[row];
            float inv = 1.f / den;
            float* og = g_o + ((size_t)bh * Nq + i0 + row) * Dq;
#pragma unroll
            for (int nt = 0; nt < 4; nt++) {
                float2 o;
                o.x = (sA * C1[mt][nt][2 * half] + sB * C2[mt][nt][2 * half]) * inv;
                o.y = (sA * C1[mt][nt][2 * half + 1] +
                       sB * C2[mt][nt][2 * half + 1]) * inv;
                *(float2*)&og[n0 + nt * 8 + c0] = o;
            }
        }
    }
}

// ---------------------------------------------------------------------------
// Kernel 5: out[b][n][d] = mean over heads of g_o
// ---------------------------------------------------------------------------
__global__ __launch_bounds__(256) void k_mean(float* __restrict__ out) {
    int idx = blockIdx.x * 256 + threadIdx.x;
    if (idx >= Bq * Nq * Dq) return;
    int d = idx & 63;
    int n = (idx >> 6) & (Nq - 1);
    int b = idx >> 17;
    float s = 0.f;
#pragma unroll
    for (int h = 0; h < Hq; h++)
        s += g_o[(((size_t)b * Hq + h) * Nq + n) * Dq + d];
    out[idx] = 0.25f * s;
}

// ---------------------------------------------------------------------------
extern "C" void kernel_launch(void* const* d_in, const int* in_sizes, int n_in,
                              void* d_out, int out_size) {
    const float* x   = (const float*)d_in[0];
    const int*   adj = (const int*)  d_in[1];
    const float* W   = (const float*)d_in[2];
    const float* a   = (const float*)d_in[3];
    float*       out = (float*)d_out;

    cudaFuncSetAttribute(k_attn, cudaFuncAttributeMaxDynamicSharedMemorySize,
                         SMEM_AT);

    k_gemm<<<(Bq * Nq) / 32, 256>>>(x, W);
    k_ev  <<<(Bq * Hq * Nq) / 8, 256>>>(a);
    k_prep<<<512 + (Bq * Nq * 64) / 256, 256>>>(adj);
    k_attn<<<Bq * Hq * (Nq / 128), 256, SMEM_AT>>>();
    k_mean<<<(Bq * Nq * Dq + 255) / 256, 256>>>(out);
}